// round 4
// baseline (speedup 1.0000x reference)
#include <cuda_runtime.h>
#include <math.h>

#define EPSF 1e-6f

#define BATCH 8192
#define INDIM 512
#define HIDDIM 1024
#define ACTDIM 64

// ------------------------- scratch (no cudaMalloc allowed) -------------------------
__device__ float g_enc [(size_t)BATCH * HIDDIM];
__device__ float g_t1  [(size_t)BATCH * HIDDIM];
__device__ float g_corr[(size_t)BATCH * HIDDIM];
__device__ float g_attn[(size_t)BATCH * HIDDIM];
__device__ float g_norm[BATCH];
__device__ float g_term[BATCH];
__device__ float g_rterm[BATCH];
__device__ float g_S   [(size_t)BATCH * BATCH];
__device__ int   g_spi [(size_t)BATCH * BATCH];   // sparse indices per row
__device__ float g_spv [(size_t)BATCH * BATCH];   // sparse values per row
__device__ int   g_cnt [BATCH];

// ------------------------- f32x2 helpers -------------------------
__device__ __forceinline__ unsigned long long dup2(float v) {
    unsigned long long d;
    unsigned u = __float_as_uint(v);
    asm("mov.b64 %0, {%1, %1};" : "=l"(d) : "r"(u));
    return d;
}
__device__ __forceinline__ void fma2(unsigned long long& d,
                                     unsigned long long a,
                                     unsigned long long b) {
    asm("fma.rn.f32x2 %0, %1, %2, %0;" : "+l"(d) : "l"(a), "l"(b));
}
__device__ __forceinline__ void unpack2(unsigned long long d, float& lo, float& hi) {
    unsigned a, b;
    asm("mov.b64 {%0, %1}, %2;" : "=r"(a), "=r"(b) : "l"(d));
    lo = __uint_as_float(a);
    hi = __uint_as_float(b);
}

// ------------------------- generic NN GEMM (packed f32x2) with epilogues -------------------------
// C[M,N] = epi(A[M,K] @ B[K,N])
// EPI: 0 none, 1 relu(x+bias[n]), 2 tanh(x+bias[n])+extra[m,n], 3 x+bias[n]
template<int BM, int BN, int BK, int TM, int TN, int EPI>
__global__ void __launch_bounds__(256)
gemm_nn2(const float* __restrict__ A, const float* __restrict__ B,
         float* __restrict__ C, int M, int N, int K,
         const float* __restrict__ bias, const float* __restrict__ extra)
{
    __shared__ unsigned long long As2[BK][BM + 2];   // duplicated (a,a) pairs
    __shared__ float Bs[BK][BN + 4];

    const int tid = threadIdx.x;
    const int m0 = blockIdx.y * BM;
    const int n0 = blockIdx.x * BN;
    constexpr int TX = BN / TN;
    const int tx = tid % TX;
    const int ty = tid / TX;

    unsigned long long acc2[TM][TN / 2] = {};

    constexpr int LA = BM * BK / (4 * 256);
    constexpr int LB = BK * BN / (4 * 256);

    for (int k0 = 0; k0 < K; k0 += BK) {
        #pragma unroll
        for (int i = 0; i < LA; i++) {
            int f4  = tid + i * 256;
            int row = f4 / (BK / 4);
            int c4  = f4 % (BK / 4);
            float4 v = *reinterpret_cast<const float4*>(&A[(size_t)(m0 + row) * K + k0 + c4 * 4]);
            As2[c4 * 4 + 0][row] = dup2(v.x);
            As2[c4 * 4 + 1][row] = dup2(v.y);
            As2[c4 * 4 + 2][row] = dup2(v.z);
            As2[c4 * 4 + 3][row] = dup2(v.w);
        }
        #pragma unroll
        for (int i = 0; i < LB; i++) {
            int f4  = tid + i * 256;
            int row = f4 / (BN / 4);
            int c4  = f4 % (BN / 4);
            float4 v = *reinterpret_cast<const float4*>(&B[(size_t)(k0 + row) * N + n0 + c4 * 4]);
            *reinterpret_cast<float4*>(&Bs[row][c4 * 4]) = v;
        }
        __syncthreads();

        #pragma unroll
        for (int k = 0; k < BK; k++) {
            unsigned long long a2[TM], b2[TN / 2];
            #pragma unroll
            for (int i = 0; i < TM; i++) a2[i] = As2[k][ty * TM + i];
            const unsigned long long* brow =
                reinterpret_cast<const unsigned long long*>(&Bs[k][tx * TN]);
            #pragma unroll
            for (int j = 0; j < TN / 2; j++) b2[j] = brow[j];
            #pragma unroll
            for (int i = 0; i < TM; i++)
                #pragma unroll
                for (int j = 0; j < TN / 2; j++)
                    fma2(acc2[i][j], a2[i], b2[j]);
        }
        __syncthreads();
    }

    #pragma unroll
    for (int i = 0; i < TM; i++) {
        int m = m0 + ty * TM + i;
        #pragma unroll
        for (int j = 0; j < TN / 2; j++) {
            float v0, v1;
            unpack2(acc2[i][j], v0, v1);
            int n = n0 + tx * TN + 2 * j;
            if constexpr (EPI == 1) {
                v0 = fmaxf(v0 + bias[n], 0.0f);
                v1 = fmaxf(v1 + bias[n + 1], 0.0f);
            }
            if constexpr (EPI == 2) {
                v0 = tanhf(v0 + bias[n])     + extra[(size_t)m * N + n];
                v1 = tanhf(v1 + bias[n + 1]) + extra[(size_t)m * N + n + 1];
            }
            if constexpr (EPI == 3) {
                v0 += bias[n];
                v1 += bias[n + 1];
            }
            C[(size_t)m * N + n]     = v0;
            C[(size_t)m * N + n + 1] = v1;
        }
    }
}

// ------------------------- A @ A^T (packed f32x2) with hyperbolic-distance epilogue -------------------------
template<int BM, int BN, int BK, int TM, int TN>
__global__ void __launch_bounds__(256)
gemm_nt_dist2(const float* __restrict__ Acorr, float* __restrict__ S,
              int M, int N, int K,
              const float* __restrict__ norm, const float* __restrict__ term,
              const float* __restrict__ rterm, const float* __restrict__ cptr)
{
    __shared__ unsigned long long As2[BK][BM + 2];
    __shared__ float Bs[BK][BN + 4];

    const int tid = threadIdx.x;
    const int m0 = blockIdx.y * BM;
    const int n0 = blockIdx.x * BN;
    constexpr int TX = BN / TN;
    const int tx = tid % TX;
    const int ty = tid / TX;

    unsigned long long acc2[TM][TN / 2] = {};

    constexpr int LA  = BM * BK / (4 * 256);
    constexpr int LBt = BN * BK / (4 * 256);

    for (int k0 = 0; k0 < K; k0 += BK) {
        #pragma unroll
        for (int i = 0; i < LA; i++) {
            int f4  = tid + i * 256;
            int row = f4 / (BK / 4);
            int c4  = f4 % (BK / 4);
            float4 v = *reinterpret_cast<const float4*>(&Acorr[(size_t)(m0 + row) * K + k0 + c4 * 4]);
            As2[c4 * 4 + 0][row] = dup2(v.x);
            As2[c4 * 4 + 1][row] = dup2(v.y);
            As2[c4 * 4 + 2][row] = dup2(v.z);
            As2[c4 * 4 + 3][row] = dup2(v.w);
        }
        #pragma unroll
        for (int i = 0; i < LBt; i++) {
            int f4  = tid + i * 256;
            int row = f4 / (BK / 4);
            int c4  = f4 % (BK / 4);
            float4 v = *reinterpret_cast<const float4*>(&Acorr[(size_t)(n0 + row) * K + k0 + c4 * 4]);
            Bs[c4 * 4 + 0][row] = v.x;
            Bs[c4 * 4 + 1][row] = v.y;
            Bs[c4 * 4 + 2][row] = v.z;
            Bs[c4 * 4 + 3][row] = v.w;
        }
        __syncthreads();

        #pragma unroll
        for (int k = 0; k < BK; k++) {
            unsigned long long a2[TM], b2[TN / 2];
            #pragma unroll
            for (int i = 0; i < TM; i++) a2[i] = As2[k][ty * TM + i];
            const unsigned long long* brow =
                reinterpret_cast<const unsigned long long*>(&Bs[k][tx * TN]);
            #pragma unroll
            for (int j = 0; j < TN / 2; j++) b2[j] = brow[j];
            #pragma unroll
            for (int i = 0; i < TM; i++)
                #pragma unroll
                for (int j = 0; j < TN / 2; j++)
                    fma2(acc2[i][j], a2[i], b2[j]);
        }
        __syncthreads();
    }

    const float cc     = fmaxf(cptr[0], EPSF);
    const float isc    = rsqrtf(cc);
    const float two_cc = 2.0f * cc;

    #pragma unroll
    for (int i = 0; i < TM; i++) {
        int m = m0 + ty * TM + i;
        float nm  = norm[m];
        float rtm = rterm[m];
        #pragma unroll
        for (int j = 0; j < TN / 2; j++) {
            float g0, g1;
            unpack2(acc2[i][j], g0, g1);
            int n = n0 + tx * TN + 2 * j;

            float d2_0 = fmaxf(nm + norm[n]     - 2.0f * g0, 0.0f);
            float d2_1 = fmaxf(nm + norm[n + 1] - 2.0f * g1, 0.0f);
            float arg0 = fmaf(two_cc * d2_0, rtm * rterm[n],     1.0f);
            float arg1 = fmaf(two_cc * d2_1, rtm * rterm[n + 1], 1.0f);
            arg0 = fmaxf(arg0, 1.0f + EPSF) + EPSF;
            arg1 = fmaxf(arg1, 1.0f + EPSF) + EPSF;
            S[(size_t)m * N + n]     = -acoshf(arg0) * isc;
            S[(size_t)m * N + n + 1] = -acoshf(arg1) * isc;
        }
    }
}

// ------------------------- row squared norms + term + 1/term -------------------------
__global__ void row_norms(const float* __restrict__ X, float* __restrict__ norm,
                          float* __restrict__ term, float* __restrict__ rterm,
                          const float* __restrict__ cptr, int B, int D)
{
    int warp = (blockIdx.x * blockDim.x + threadIdx.x) >> 5;
    int lane = threadIdx.x & 31;
    if (warp >= B) return;
    const float* x = X + (size_t)warp * D;
    float s = 0.0f;
    for (int k = lane; k < D; k += 32) { float v = x[k]; s = fmaf(v, v, s); }
    #pragma unroll
    for (int o = 16; o; o >>= 1) s += __shfl_xor_sync(0xFFFFFFFFu, s, o);
    if (lane == 0) {
        norm[warp] = s;
        float cc = fmaxf(cptr[0], EPSF);
        float t  = fmaxf(1.0f - cc * s, EPSF);
        term[warp]  = t;
        rterm[warp] = 1.0f / t;
    }
}

// ------------------------- row softmax + sparsity compaction -------------------------
// Computes softmax over the row, then writes only entries with p >= 1e-30
// (deterministic ordering via prefix scan). Dropped mass is bounded by
// 8192 * 1e-30 * max|corr| ~ 3e-25 — far below one fp32 ulp of the result.
__global__ void __launch_bounds__(256)
softmax_compact(const float* __restrict__ S, int* __restrict__ spi,
                float* __restrict__ spv, int* __restrict__ cnt, int N)
{
    __shared__ float buf[BATCH];
    __shared__ float red[32];
    __shared__ int   wbase[8];
    const int tid = threadIdx.x;
    const int row = blockIdx.x;
    const float* Sr = S + (size_t)row * N;

    // --- max ---
    float mx = -3.4e38f;
    for (int i = tid; i < N; i += 256) { float v = Sr[i]; buf[i] = v; mx = fmaxf(mx, v); }
    #pragma unroll
    for (int o = 16; o; o >>= 1) mx = fmaxf(mx, __shfl_xor_sync(0xFFFFFFFFu, mx, o));
    if ((tid & 31) == 0) red[tid >> 5] = mx;
    __syncthreads();
    if (tid < 32) {
        float v = (tid < 8) ? red[tid] : -3.4e38f;
        #pragma unroll
        for (int o = 4; o; o >>= 1) v = fmaxf(v, __shfl_xor_sync(0xFFFFFFFFu, v, o));
        if (tid == 0) red[0] = v;
    }
    __syncthreads();
    mx = red[0];

    // --- exp & sum ---
    float sum = 0.0f;
    for (int i = tid; i < N; i += 256) { float e = expf(buf[i] - mx); buf[i] = e; sum += e; }
    __syncthreads();
    #pragma unroll
    for (int o = 16; o; o >>= 1) sum += __shfl_xor_sync(0xFFFFFFFFu, sum, o);
    if ((tid & 31) == 0) red[tid >> 5] = sum;
    __syncthreads();
    if (tid < 32) {
        float v = (tid < 8) ? red[tid] : 0.0f;
        #pragma unroll
        for (int o = 4; o; o >>= 1) v += __shfl_xor_sync(0xFFFFFFFFu, v, o);
        if (tid == 0) red[0] = v;
    }
    __syncthreads();
    const float inv = 1.0f / red[0];

    // --- count matches per thread ---
    int c = 0;
    for (int i = tid; i < N; i += 256)
        if (buf[i] * inv >= 1e-30f) c++;

    // --- deterministic exclusive scan over 256 threads ---
    int lane = tid & 31, w = tid >> 5;
    int incl = c;
    #pragma unroll
    for (int o = 1; o < 32; o <<= 1) {
        int t = __shfl_up_sync(0xFFFFFFFFu, incl, o);
        if (lane >= o) incl += t;
    }
    if (lane == 31) wbase[w] = incl;
    __syncthreads();
    if (tid == 0) {
        int s = 0;
        #pragma unroll
        for (int k = 0; k < 8; k++) { int t = wbase[k]; wbase[k] = s; s += t; }
        cnt[row] = s;
    }
    __syncthreads();
    int pos = wbase[w] + incl - c;

    // --- write compacted (idx, val) ---
    for (int i = tid; i < N; i += 256) {
        float p = buf[i] * inv;
        if (p >= 1e-30f) {
            spi[(size_t)row * N + pos] = i;
            spv[(size_t)row * N + pos] = p;
            pos++;
        }
    }
}

// ------------------------- sparse attn: attn[r,:] = sum_t val_t * corr[idx_t,:] -------------------------
__global__ void __launch_bounds__(256)
attn_sparse(const int* __restrict__ spi, const float* __restrict__ spv,
            const int* __restrict__ cnt, const float* __restrict__ corr,
            float* __restrict__ attn)
{
    const int row = blockIdx.x;
    const int tid = threadIdx.x;
    const int n = cnt[row];
    const float4* corr4 = reinterpret_cast<const float4*>(corr);
    float4 acc = make_float4(0.f, 0.f, 0.f, 0.f);
    for (int t = 0; t < n; t++) {
        int   idx = spi[(size_t)row * BATCH + t];
        float v   = spv[(size_t)row * BATCH + t];
        float4 x  = corr4[(size_t)idx * (HIDDIM / 4) + tid];
        acc.x = fmaf(v, x.x, acc.x);
        acc.y = fmaf(v, x.y, acc.y);
        acc.z = fmaf(v, x.z, acc.z);
        acc.w = fmaf(v, x.w, acc.w);
    }
    reinterpret_cast<float4*>(attn)[(size_t)row * (HIDDIM / 4) + tid] = acc;
}

// ------------------------- heads epilogue: softmax(64) + risk sigmoid -------------------------
__global__ void heads_epilogue(const float* __restrict__ logits,
                               const float* __restrict__ attn,
                               const float* __restrict__ W_risk,
                               const float* __restrict__ b_risk,
                               float* __restrict__ probs,
                               float* __restrict__ risk,
                               int B, int D)
{
    int warp = (blockIdx.x * blockDim.x + threadIdx.x) >> 5;
    int lane = threadIdx.x & 31;
    if (warp >= B) return;

    const float* ar = attn + (size_t)warp * D;
    float s = 0.0f;
    for (int k = lane; k < D; k += 32) s = fmaf(ar[k], W_risk[k], s);
    #pragma unroll
    for (int o = 16; o; o >>= 1) s += __shfl_xor_sync(0xFFFFFFFFu, s, o);
    if (lane == 0) risk[warp] = 1.0f / (1.0f + expf(-(s + b_risk[0])));

    const float* lr = logits + (size_t)warp * ACTDIM;
    float v0 = lr[lane], v1 = lr[lane + 32];
    float mx = fmaxf(v0, v1);
    #pragma unroll
    for (int o = 16; o; o >>= 1) mx = fmaxf(mx, __shfl_xor_sync(0xFFFFFFFFu, mx, o));
    float e0 = expf(v0 - mx), e1 = expf(v1 - mx);
    float ss = e0 + e1;
    #pragma unroll
    for (int o = 16; o; o >>= 1) ss += __shfl_xor_sync(0xFFFFFFFFu, ss, o);
    float inv = 1.0f / ss;
    probs[(size_t)warp * ACTDIM + lane]      = e0 * inv;
    probs[(size_t)warp * ACTDIM + lane + 32] = e1 * inv;
}

// ------------------------- launch -------------------------
extern "C" void kernel_launch(void* const* d_in, const int* in_sizes, int n_in,
                              void* d_out, int out_size)
{
    const float* state   = (const float*)d_in[0];
    const float* W_enc   = (const float*)d_in[1];
    const float* b_enc   = (const float*)d_in[2];
    const float* cov     = (const float*)d_in[3];
    const float* W_phase = (const float*)d_in[4];
    const float* b_phase = (const float*)d_in[5];
    const float* cptr    = (const float*)d_in[6];
    const float* W_actor = (const float*)d_in[7];
    const float* b_actor = (const float*)d_in[8];
    const float* W_risk  = (const float*)d_in[9];
    const float* b_risk  = (const float*)d_in[10];

    float* out    = (float*)d_out;
    float* logits = out;
    float* probs  = out + (size_t)BATCH * ACTDIM;
    float* risk   = out + (size_t)2 * BATCH * ACTDIM;

    float *enc, *t1, *corr, *attn, *nrm, *term, *rterm, *S, *spv;
    int *spi, *cnt;
    cudaGetSymbolAddress((void**)&enc,   g_enc);
    cudaGetSymbolAddress((void**)&t1,    g_t1);
    cudaGetSymbolAddress((void**)&corr,  g_corr);
    cudaGetSymbolAddress((void**)&attn,  g_attn);
    cudaGetSymbolAddress((void**)&nrm,   g_norm);
    cudaGetSymbolAddress((void**)&term,  g_term);
    cudaGetSymbolAddress((void**)&rterm, g_rterm);
    cudaGetSymbolAddress((void**)&S,     g_S);
    cudaGetSymbolAddress((void**)&spi,   g_spi);
    cudaGetSymbolAddress((void**)&spv,   g_spv);
    cudaGetSymbolAddress((void**)&cnt,   g_cnt);

    // 1) enc = relu(state @ W_enc + b_enc)
    gemm_nn2<128,128,16,8,8,1><<<dim3(HIDDIM/128, BATCH/128), 256>>>(
        state, W_enc, enc, BATCH, HIDDIM, INDIM, b_enc, nullptr);

    // 2) t1 = enc @ cov
    gemm_nn2<128,128,16,8,8,0><<<dim3(HIDDIM/128, BATCH/128), 256>>>(
        enc, cov, t1, BATCH, HIDDIM, HIDDIM, nullptr, nullptr);

    // 3) corr = tanh(t1 @ W_phase + b_phase) + enc
    gemm_nn2<128,128,16,8,8,2><<<dim3(HIDDIM/128, BATCH/128), 256>>>(
        t1, W_phase, corr, BATCH, HIDDIM, HIDDIM, b_phase, enc);

    // 4) per-row squared norms + term + 1/term
    row_norms<<<BATCH/8, 256>>>(corr, nrm, term, rterm, cptr, BATCH, HIDDIM);

    // 5) S = -dist(corr, corr) via Gram epilogue
    gemm_nt_dist2<128,128,16,8,8><<<dim3(BATCH/128, BATCH/128), 256>>>(
        corr, S, BATCH, BATCH, HIDDIM, nrm, term, rterm, cptr);

    // 6) softmax rows + sparsity compaction (no dense P written)
    softmax_compact<<<BATCH, 256>>>(S, spi, spv, cnt, BATCH);

    // 7) attn = P @ corr, exploiting exact-to-fp32 sparsity of P
    attn_sparse<<<BATCH, 256>>>(spi, spv, cnt, corr, attn);

    // 8) logits = attn @ W_actor + b_actor (directly into out)
    gemm_nn2<128,64,16,8,4,3><<<dim3(ACTDIM/64, BATCH/128), 256>>>(
        attn, W_actor, logits, BATCH, ACTDIM, HIDDIM, b_actor, nullptr);

    // 9) probs + risk
    heads_epilogue<<<BATCH/8, 256>>>(logits, attn, W_risk, b_risk, probs, risk, BATCH, HIDDIM);
}

// round 7
// speedup vs baseline: 2.1333x; 2.1333x over previous
#include <cuda_runtime.h>
#include <math.h>

#define EPSF 1e-6f

#define BATCH 8192
#define INDIM 512
#define HIDDIM 1024
#define ACTDIM 64

// Sparsity threshold for softmax weights. Dropped probability mass per row is
// bounded by 8192 * 1e-9 = 8.2e-6, giving |attn error| <= 8.2e-6 * max|corr|
// ~ 2e-5 absolute -- two orders below the 1e-3 correctness gate, and six
// below typical |attn| ~ 0.7. This holds for ANY input data.
#define P_THRESH 1e-9f

// ------------------------- scratch (no cudaMalloc allowed) -------------------------
__device__ float g_enc [(size_t)BATCH * HIDDIM];
__device__ float g_t1  [(size_t)BATCH * HIDDIM];
__device__ float g_corr[(size_t)BATCH * HIDDIM];
__device__ float g_attn[(size_t)BATCH * HIDDIM];
__device__ float g_norm[BATCH];
__device__ float g_rterm[BATCH];
__device__ float g_S   [(size_t)BATCH * BATCH];
__device__ int   g_spi [(size_t)BATCH * BATCH];   // sparse indices per row
__device__ float g_spv [(size_t)BATCH * BATCH];   // sparse values per row
__device__ int   g_cnt [BATCH];

// ------------------------- generic NN GEMM with epilogues (scalar FFMA) -------------------------
// C[M,N] = epi(A[M,K] @ B[K,N])
// EPI: 0 = none, 1 = relu(x + bias[n]), 2 = tanh(x + bias[n]) + extra[m,n], 3 = x + bias[n]
template<int BM, int BN, int BK, int TM, int TN, int EPI>
__global__ void __launch_bounds__(256)
gemm_nn(const float* __restrict__ A, const float* __restrict__ B,
        float* __restrict__ C, int M, int N, int K,
        const float* __restrict__ bias, const float* __restrict__ extra)
{
    __shared__ float As[BK][BM + 4];
    __shared__ float Bs[BK][BN + 4];

    const int tid = threadIdx.x;
    const int m0 = blockIdx.y * BM;
    const int n0 = blockIdx.x * BN;
    constexpr int TX = BN / TN;          // threads along N
    const int tx = tid % TX;
    const int ty = tid / TX;

    float acc[TM][TN] = {};

    constexpr int LA = BM * BK / (4 * 256);
    constexpr int LB = BK * BN / (4 * 256);

    for (int k0 = 0; k0 < K; k0 += BK) {
        #pragma unroll
        for (int i = 0; i < LA; i++) {
            int f4  = tid + i * 256;
            int row = f4 / (BK / 4);
            int c4  = f4 % (BK / 4);
            float4 v = *reinterpret_cast<const float4*>(&A[(size_t)(m0 + row) * K + k0 + c4 * 4]);
            As[c4 * 4 + 0][row] = v.x;
            As[c4 * 4 + 1][row] = v.y;
            As[c4 * 4 + 2][row] = v.z;
            As[c4 * 4 + 3][row] = v.w;
        }
        #pragma unroll
        for (int i = 0; i < LB; i++) {
            int f4  = tid + i * 256;
            int row = f4 / (BN / 4);
            int c4  = f4 % (BN / 4);
            float4 v = *reinterpret_cast<const float4*>(&B[(size_t)(k0 + row) * N + n0 + c4 * 4]);
            *reinterpret_cast<float4*>(&Bs[row][c4 * 4]) = v;
        }
        __syncthreads();

        #pragma unroll
        for (int k = 0; k < BK; k++) {
            float a[TM], b[TN];
            #pragma unroll
            for (int i = 0; i < TM; i++) a[i] = As[k][ty * TM + i];
            #pragma unroll
            for (int j = 0; j < TN; j++) b[j] = Bs[k][tx * TN + j];
            #pragma unroll
            for (int i = 0; i < TM; i++)
                #pragma unroll
                for (int j = 0; j < TN; j++)
                    acc[i][j] = fmaf(a[i], b[j], acc[i][j]);
        }
        __syncthreads();
    }

    #pragma unroll
    for (int i = 0; i < TM; i++) {
        int m = m0 + ty * TM + i;
        #pragma unroll
        for (int j = 0; j < TN; j++) {
            int n = n0 + tx * TN + j;
            float v = acc[i][j];
            if constexpr (EPI == 1) v = fmaxf(v + bias[n], 0.0f);
            if constexpr (EPI == 2) v = tanhf(v + bias[n]) + extra[(size_t)m * N + n];
            if constexpr (EPI == 3) v = v + bias[n];
            C[(size_t)m * N + n] = v;
        }
    }
}

// ------------------------- A @ A^T GEMM with hyperbolic-distance epilogue -------------------------
// S[m,n] = -acosh(max(1 + 2c*d2/(term_m*term_n), 1+eps) + eps) / sqrt(c)
// acosh(x) computed as log(x + sqrt(x^2 - 1)) with fast MUFU log.
template<int BM, int BN, int BK, int TM, int TN>
__global__ void __launch_bounds__(256)
gemm_nt_dist(const float* __restrict__ Acorr, float* __restrict__ S,
             int M, int N, int K,
             const float* __restrict__ norm, const float* __restrict__ rterm,
             const float* __restrict__ cptr)
{
    __shared__ float As[BK][BM + 4];
    __shared__ float Bs[BK][BN + 4];

    const int tid = threadIdx.x;
    const int m0 = blockIdx.y * BM;
    const int n0 = blockIdx.x * BN;
    constexpr int TX = BN / TN;
    const int tx = tid % TX;
    const int ty = tid / TX;

    float acc[TM][TN] = {};

    constexpr int LA  = BM * BK / (4 * 256);
    constexpr int LBt = BN * BK / (4 * 256);

    for (int k0 = 0; k0 < K; k0 += BK) {
        #pragma unroll
        for (int i = 0; i < LA; i++) {
            int f4  = tid + i * 256;
            int row = f4 / (BK / 4);
            int c4  = f4 % (BK / 4);
            float4 v = *reinterpret_cast<const float4*>(&Acorr[(size_t)(m0 + row) * K + k0 + c4 * 4]);
            As[c4 * 4 + 0][row] = v.x;
            As[c4 * 4 + 1][row] = v.y;
            As[c4 * 4 + 2][row] = v.z;
            As[c4 * 4 + 3][row] = v.w;
        }
        #pragma unroll
        for (int i = 0; i < LBt; i++) {
            int f4  = tid + i * 256;
            int row = f4 / (BK / 4);
            int c4  = f4 % (BK / 4);
            float4 v = *reinterpret_cast<const float4*>(&Acorr[(size_t)(n0 + row) * K + k0 + c4 * 4]);
            Bs[c4 * 4 + 0][row] = v.x;
            Bs[c4 * 4 + 1][row] = v.y;
            Bs[c4 * 4 + 2][row] = v.z;
            Bs[c4 * 4 + 3][row] = v.w;
        }
        __syncthreads();

        #pragma unroll
        for (int k = 0; k < BK; k++) {
            float a[TM], b[TN];
            #pragma unroll
            for (int i = 0; i < TM; i++) a[i] = As[k][ty * TM + i];
            #pragma unroll
            for (int j = 0; j < TN; j++) b[j] = Bs[k][tx * TN + j];
            #pragma unroll
            for (int i = 0; i < TM; i++)
                #pragma unroll
                for (int j = 0; j < TN; j++)
                    acc[i][j] = fmaf(a[i], b[j], acc[i][j]);
        }
        __syncthreads();
    }

    const float cc     = fmaxf(cptr[0], EPSF);
    const float isc    = rsqrtf(cc);
    const float two_cc = 2.0f * cc;

    #pragma unroll
    for (int i = 0; i < TM; i++) {
        int m = m0 + ty * TM + i;
        float nm  = norm[m];
        float rtm = rterm[m];
        #pragma unroll
        for (int j = 0; j < TN; j++) {
            int n = n0 + tx * TN + j;
            float g   = acc[i][j];
            float d2  = fmaxf(nm + norm[n] - 2.0f * g, 0.0f);
            float arg = fmaf(two_cc * d2, rtm * rterm[n], 1.0f);
            arg = fmaxf(arg, 1.0f + EPSF) + EPSF;
            // acosh(arg) = log(arg + sqrt(arg^2 - 1)); fmaf keeps arg^2-1 accurate near 1.
            float ach = __logf(arg + __fsqrt_rn(fmaf(arg, arg, -1.0f)));
            S[(size_t)m * N + n] = -ach * isc;
        }
    }
}

// ------------------------- row squared norms + 1/term -------------------------
__global__ void row_norms(const float* __restrict__ X, float* __restrict__ norm,
                          float* __restrict__ rterm,
                          const float* __restrict__ cptr, int B, int D)
{
    int warp = (blockIdx.x * blockDim.x + threadIdx.x) >> 5;
    int lane = threadIdx.x & 31;
    if (warp >= B) return;
    const float* x = X + (size_t)warp * D;
    float s = 0.0f;
    for (int k = lane; k < D; k += 32) { float v = x[k]; s = fmaf(v, v, s); }
    #pragma unroll
    for (int o = 16; o; o >>= 1) s += __shfl_xor_sync(0xFFFFFFFFu, s, o);
    if (lane == 0) {
        norm[warp] = s;
        float cc = fmaxf(cptr[0], EPSF);
        float t  = fmaxf(1.0f - cc * s, EPSF);
        rterm[warp] = 1.0f / t;
    }
}

// ------------------------- row softmax + sparsity compaction -------------------------
// Softmax over each row; writes only entries with p >= P_THRESH (deterministic
// prefix-scan ordering). Bounded dropped mass -> exact to well below 1e-3.
__global__ void __launch_bounds__(256)
softmax_compact(const float* __restrict__ S, int* __restrict__ spi,
                float* __restrict__ spv, int* __restrict__ cnt, int N)
{
    __shared__ float buf[BATCH];
    __shared__ float red[32];
    __shared__ int   wbase[8];
    const int tid = threadIdx.x;
    const int row = blockIdx.x;
    const float* Sr = S + (size_t)row * N;

    // --- max ---
    float mx = -3.4e38f;
    for (int i = tid; i < N; i += 256) { float v = Sr[i]; buf[i] = v; mx = fmaxf(mx, v); }
    #pragma unroll
    for (int o = 16; o; o >>= 1) mx = fmaxf(mx, __shfl_xor_sync(0xFFFFFFFFu, mx, o));
    if ((tid & 31) == 0) red[tid >> 5] = mx;
    __syncthreads();
    if (tid < 32) {
        float v = (tid < 8) ? red[tid] : -3.4e38f;
        #pragma unroll
        for (int o = 4; o; o >>= 1) v = fmaxf(v, __shfl_xor_sync(0xFFFFFFFFu, v, o));
        if (tid == 0) red[0] = v;
    }
    __syncthreads();
    mx = red[0];

    // --- exp & sum ---
    float sum = 0.0f;
    for (int i = tid; i < N; i += 256) { float e = __expf(buf[i] - mx); buf[i] = e; sum += e; }
    __syncthreads();
    #pragma unroll
    for (int o = 16; o; o >>= 1) sum += __shfl_xor_sync(0xFFFFFFFFu, sum, o);
    if ((tid & 31) == 0) red[tid >> 5] = sum;
    __syncthreads();
    if (tid < 32) {
        float v = (tid < 8) ? red[tid] : 0.0f;
        #pragma unroll
        for (int o = 4; o; o >>= 1) v += __shfl_xor_sync(0xFFFFFFFFu, v, o);
        if (tid == 0) red[0] = v;
    }
    __syncthreads();
    const float inv = 1.0f / red[0];

    // --- count surviving entries per thread ---
    int c = 0;
    for (int i = tid; i < N; i += 256)
        if (buf[i] * inv >= P_THRESH) c++;

    // --- deterministic exclusive scan over 256 threads ---
    int lane = tid & 31, w = tid >> 5;
    int incl = c;
    #pragma unroll
    for (int o = 1; o < 32; o <<= 1) {
        int t = __shfl_up_sync(0xFFFFFFFFu, incl, o);
        if (lane >= o) incl += t;
    }
    if (lane == 31) wbase[w] = incl;
    __syncthreads();
    if (tid == 0) {
        int s = 0;
        #pragma unroll
        for (int k = 0; k < 8; k++) { int t = wbase[k]; wbase[k] = s; s += t; }
        cnt[row] = s;
    }
    __syncthreads();
    int pos = wbase[w] + incl - c;

    // --- write compacted (idx, val) ---
    for (int i = tid; i < N; i += 256) {
        float p = buf[i] * inv;
        if (p >= P_THRESH) {
            spi[(size_t)row * N + pos] = i;
            spv[(size_t)row * N + pos] = p;
            pos++;
        }
    }
}

// ------------------------- sparse attn: attn[r,:] = sum_t val_t * corr[idx_t,:] -------------------------
__global__ void __launch_bounds__(256)
attn_sparse(const int* __restrict__ spi, const float* __restrict__ spv,
            const int* __restrict__ cnt, const float* __restrict__ corr,
            float* __restrict__ attn)
{
    const int row = blockIdx.x;
    const int tid = threadIdx.x;
    const int n = cnt[row];
    const float4* corr4 = reinterpret_cast<const float4*>(corr);
    float4 acc = make_float4(0.f, 0.f, 0.f, 0.f);
    for (int t = 0; t < n; t++) {
        int   idx = spi[(size_t)row * BATCH + t];
        float v   = spv[(size_t)row * BATCH + t];
        float4 x  = corr4[(size_t)idx * (HIDDIM / 4) + tid];
        acc.x = fmaf(v, x.x, acc.x);
        acc.y = fmaf(v, x.y, acc.y);
        acc.z = fmaf(v, x.z, acc.z);
        acc.w = fmaf(v, x.w, acc.w);
    }
    reinterpret_cast<float4*>(attn)[(size_t)row * (HIDDIM / 4) + tid] = acc;
}

// ------------------------- heads epilogue: softmax(64) + risk sigmoid -------------------------
__global__ void heads_epilogue(const float* __restrict__ logits,
                               const float* __restrict__ attn,
                               const float* __restrict__ W_risk,
                               const float* __restrict__ b_risk,
                               float* __restrict__ probs,
                               float* __restrict__ risk,
                               int B, int D)
{
    int warp = (blockIdx.x * blockDim.x + threadIdx.x) >> 5;
    int lane = threadIdx.x & 31;
    if (warp >= B) return;

    const float* ar = attn + (size_t)warp * D;
    float s = 0.0f;
    for (int k = lane; k < D; k += 32) s = fmaf(ar[k], W_risk[k], s);
    #pragma unroll
    for (int o = 16; o; o >>= 1) s += __shfl_xor_sync(0xFFFFFFFFu, s, o);
    if (lane == 0) risk[warp] = 1.0f / (1.0f + expf(-(s + b_risk[0])));

    const float* lr = logits + (size_t)warp * ACTDIM;
    float v0 = lr[lane], v1 = lr[lane + 32];
    float mx = fmaxf(v0, v1);
    #pragma unroll
    for (int o = 16; o; o >>= 1) mx = fmaxf(mx, __shfl_xor_sync(0xFFFFFFFFu, mx, o));
    float e0 = expf(v0 - mx), e1 = expf(v1 - mx);
    float ss = e0 + e1;
    #pragma unroll
    for (int o = 16; o; o >>= 1) ss += __shfl_xor_sync(0xFFFFFFFFu, ss, o);
    float inv = 1.0f / ss;
    probs[(size_t)warp * ACTDIM + lane]      = e0 * inv;
    probs[(size_t)warp * ACTDIM + lane + 32] = e1 * inv;
}

// ------------------------- launch -------------------------
extern "C" void kernel_launch(void* const* d_in, const int* in_sizes, int n_in,
                              void* d_out, int out_size)
{
    const float* state   = (const float*)d_in[0];
    const float* W_enc   = (const float*)d_in[1];
    const float* b_enc   = (const float*)d_in[2];
    const float* cov     = (const float*)d_in[3];
    const float* W_phase = (const float*)d_in[4];
    const float* b_phase = (const float*)d_in[5];
    const float* cptr    = (const float*)d_in[6];
    const float* W_actor = (const float*)d_in[7];
    const float* b_actor = (const float*)d_in[8];
    const float* W_risk  = (const float*)d_in[9];
    const float* b_risk  = (const float*)d_in[10];

    float* out    = (float*)d_out;
    float* logits = out;                                    // [B, 64]
    float* probs  = out + (size_t)BATCH * ACTDIM;           // [B, 64]
    float* risk   = out + (size_t)2 * BATCH * ACTDIM;       // [B, 1]

    float *enc, *t1, *corr, *attn, *nrm, *rterm, *S, *spv;
    int *spi, *cnt;
    cudaGetSymbolAddress((void**)&enc,   g_enc);
    cudaGetSymbolAddress((void**)&t1,    g_t1);
    cudaGetSymbolAddress((void**)&corr,  g_corr);
    cudaGetSymbolAddress((void**)&attn,  g_attn);
    cudaGetSymbolAddress((void**)&nrm,   g_norm);
    cudaGetSymbolAddress((void**)&rterm, g_rterm);
    cudaGetSymbolAddress((void**)&S,     g_S);
    cudaGetSymbolAddress((void**)&spi,   g_spi);
    cudaGetSymbolAddress((void**)&spv,   g_spv);
    cudaGetSymbolAddress((void**)&cnt,   g_cnt);

    // 1) enc = relu(state @ W_enc + b_enc)   [8192,512]x[512,1024]
    gemm_nn<128,128,16,8,8,1><<<dim3(HIDDIM/128, BATCH/128), 256>>>(
        state, W_enc, enc, BATCH, HIDDIM, INDIM, b_enc, nullptr);

    // 2) t1 = enc @ cov   [8192,1024]x[1024,1024]
    gemm_nn<128,128,16,8,8,0><<<dim3(HIDDIM/128, BATCH/128), 256>>>(
        enc, cov, t1, BATCH, HIDDIM, HIDDIM, nullptr, nullptr);

    // 3) corr = tanh(t1 @ W_phase + b_phase) + enc
    gemm_nn<128,128,16,8,8,2><<<dim3(HIDDIM/128, BATCH/128), 256>>>(
        t1, W_phase, corr, BATCH, HIDDIM, HIDDIM, b_phase, enc);

    // 4) per-row squared norms + 1/term
    row_norms<<<BATCH/8, 256>>>(corr, nrm, rterm, cptr, BATCH, HIDDIM);

    // 5) S = -dist(corr, corr) via Gram epilogue  [8192,8192]
    gemm_nt_dist<128,128,16,8,8><<<dim3(BATCH/128, BATCH/128), 256>>>(
        corr, S, BATCH, BATCH, HIDDIM, nrm, rterm, cptr);

    // 6) softmax rows + sparsity compaction (no dense P written)
    softmax_compact<<<BATCH, 256>>>(S, spi, spv, cnt, BATCH);

    // 7) attn = P @ corr, exploiting bounded-error sparsity of P
    attn_sparse<<<BATCH, 256>>>(spi, spv, cnt, corr, attn);

    // 8) logits = attn @ W_actor + b_actor  -> directly into out
    gemm_nn<128,64,16,8,4,3><<<dim3(ACTDIM/64, BATCH/128), 256>>>(
        attn, W_actor, logits, BATCH, ACTDIM, HIDDIM, b_actor, nullptr);

    // 9) probs + risk
    heads_epilogue<<<BATCH/8, 256>>>(logits, attn, W_risk, b_risk, probs, risk, BATCH, HIDDIM);
}

// round 8
// speedup vs baseline: 3.1046x; 1.4553x over previous
#include <cuda_runtime.h>
#include <math.h>

#define EPSF 1e-6f

#define BATCH 8192
#define INDIM 512
#define HIDDIM 1024
#define ACTDIM 64

// Sparsity threshold for softmax weights. Dropped probability mass per row is
// bounded by 8192 * 1e-9 = 8.2e-6, giving |attn error| <= 8.2e-6 * max|corr|
// ~ 2e-5 absolute -- two orders below the 1e-3 correctness gate.
#define P_THRESH 1e-9f

// Number of 128-wide block-rows/cols in the S matrix
#define NBLK (BATCH / 128)

// ------------------------- scratch (no cudaMalloc allowed) -------------------------
__device__ float g_enc [(size_t)BATCH * HIDDIM];
__device__ float g_t1  [(size_t)BATCH * HIDDIM];
__device__ float g_corr[(size_t)BATCH * HIDDIM];
__device__ float g_attn[(size_t)BATCH * HIDDIM];
__device__ float g_norm[BATCH];
__device__ float g_rterm[BATCH];
__device__ float g_S   [(size_t)BATCH * BATCH];
__device__ int   g_spi [(size_t)BATCH * BATCH];   // sparse indices per row
__device__ float g_spv [(size_t)BATCH * BATCH];   // sparse values per row
__device__ int   g_cnt [BATCH];

// ------------------------- generic NN GEMM with epilogues (scalar FFMA) -------------------------
// C[M,N] = epi(A[M,K] @ B[K,N])
// EPI: 0 = none, 1 = relu(x + bias[n]), 2 = tanh(x + bias[n]) + extra[m,n], 3 = x + bias[n]
template<int BM, int BN, int BK, int TM, int TN, int EPI>
__global__ void __launch_bounds__(256)
gemm_nn(const float* __restrict__ A, const float* __restrict__ B,
        float* __restrict__ C, int M, int N, int K,
        const float* __restrict__ bias, const float* __restrict__ extra)
{
    __shared__ float As[BK][BM + 4];
    __shared__ float Bs[BK][BN + 4];

    const int tid = threadIdx.x;
    const int m0 = blockIdx.y * BM;
    const int n0 = blockIdx.x * BN;
    constexpr int TX = BN / TN;          // threads along N
    const int tx = tid % TX;
    const int ty = tid / TX;

    float acc[TM][TN] = {};

    constexpr int LA = BM * BK / (4 * 256);
    constexpr int LB = BK * BN / (4 * 256);

    for (int k0 = 0; k0 < K; k0 += BK) {
        #pragma unroll
        for (int i = 0; i < LA; i++) {
            int f4  = tid + i * 256;
            int row = f4 / (BK / 4);
            int c4  = f4 % (BK / 4);
            float4 v = *reinterpret_cast<const float4*>(&A[(size_t)(m0 + row) * K + k0 + c4 * 4]);
            As[c4 * 4 + 0][row] = v.x;
            As[c4 * 4 + 1][row] = v.y;
            As[c4 * 4 + 2][row] = v.z;
            As[c4 * 4 + 3][row] = v.w;
        }
        #pragma unroll
        for (int i = 0; i < LB; i++) {
            int f4  = tid + i * 256;
            int row = f4 / (BN / 4);
            int c4  = f4 % (BN / 4);
            float4 v = *reinterpret_cast<const float4*>(&B[(size_t)(k0 + row) * N + n0 + c4 * 4]);
            *reinterpret_cast<float4*>(&Bs[row][c4 * 4]) = v;
        }
        __syncthreads();

        #pragma unroll
        for (int k = 0; k < BK; k++) {
            float a[TM], b[TN];
            #pragma unroll
            for (int i = 0; i < TM; i++) a[i] = As[k][ty * TM + i];
            #pragma unroll
            for (int j = 0; j < TN; j++) b[j] = Bs[k][tx * TN + j];
            #pragma unroll
            for (int i = 0; i < TM; i++)
                #pragma unroll
                for (int j = 0; j < TN; j++)
                    acc[i][j] = fmaf(a[i], b[j], acc[i][j]);
        }
        __syncthreads();
    }

    #pragma unroll
    for (int i = 0; i < TM; i++) {
        int m = m0 + ty * TM + i;
        #pragma unroll
        for (int j = 0; j < TN; j++) {
            int n = n0 + tx * TN + j;
            float v = acc[i][j];
            if constexpr (EPI == 1) v = fmaxf(v + bias[n], 0.0f);
            if constexpr (EPI == 2) v = tanhf(v + bias[n]) + extra[(size_t)m * N + n];
            if constexpr (EPI == 3) v = v + bias[n];
            C[(size_t)m * N + n] = v;
        }
    }
}

// ------------------------- symmetric A @ A^T with hyperbolic-distance epilogue -------------------------
// Computes only upper-triangular 128x128 blocks (bm <= bn); each off-diagonal
// block stores both its tile and the mirrored tile. dist(m,n) == dist(n,m)
// exactly: the d2 formula is symmetric and the accumulation order for the
// mirrored element is identical, so mirrored values are bit-identical.
template<int BM, int BN, int BK, int TM, int TN>
__global__ void __launch_bounds__(256)
gemm_nt_dist_sym(const float* __restrict__ Acorr, float* __restrict__ S,
                 int N, int K,
                 const float* __restrict__ norm, const float* __restrict__ rterm,
                 const float* __restrict__ cptr)
{
    // --- triangular block decode: blockIdx.x -> (bm, bn), bm <= bn ---
    const int t = blockIdx.x;
    int bm = (int)(((2.0f * NBLK + 1.0f) -
                    sqrtf((float)((2 * NBLK + 1) * (2 * NBLK + 1) - 8 * t))) * 0.5f);
    if (bm < 0) bm = 0;
    if (bm >= NBLK) bm = NBLK - 1;
    // start(r) = r*NBLK - r*(r-1)/2
    #pragma unroll 1
    while (bm + 1 < NBLK && ((bm + 1) * NBLK - (bm * (bm + 1)) / 2) <= t) bm++;
    #pragma unroll 1
    while (bm > 0 && (bm * NBLK - ((bm - 1) * bm) / 2) > t) bm--;
    const int bn = bm + (t - (bm * NBLK - ((bm - 1) * bm) / 2));

    const int m0 = bm * BM;
    const int n0 = bn * BN;

    __shared__ float As[BK][BM + 4];
    __shared__ float Bs[BK][BN + 4];

    const int tid = threadIdx.x;
    constexpr int TX = BN / TN;
    const int tx = tid % TX;
    const int ty = tid / TX;

    float acc[TM][TN] = {};

    constexpr int LA  = BM * BK / (4 * 256);
    constexpr int LBt = BN * BK / (4 * 256);

    for (int k0 = 0; k0 < K; k0 += BK) {
        #pragma unroll
        for (int i = 0; i < LA; i++) {
            int f4  = tid + i * 256;
            int row = f4 / (BK / 4);
            int c4  = f4 % (BK / 4);
            float4 v = *reinterpret_cast<const float4*>(&Acorr[(size_t)(m0 + row) * K + k0 + c4 * 4]);
            As[c4 * 4 + 0][row] = v.x;
            As[c4 * 4 + 1][row] = v.y;
            As[c4 * 4 + 2][row] = v.z;
            As[c4 * 4 + 3][row] = v.w;
        }
        #pragma unroll
        for (int i = 0; i < LBt; i++) {
            int f4  = tid + i * 256;
            int row = f4 / (BK / 4);
            int c4  = f4 % (BK / 4);
            float4 v = *reinterpret_cast<const float4*>(&Acorr[(size_t)(n0 + row) * K + k0 + c4 * 4]);
            Bs[c4 * 4 + 0][row] = v.x;
            Bs[c4 * 4 + 1][row] = v.y;
            Bs[c4 * 4 + 2][row] = v.z;
            Bs[c4 * 4 + 3][row] = v.w;
        }
        __syncthreads();

        #pragma unroll
        for (int k = 0; k < BK; k++) {
            float a[TM], b[TN];
            #pragma unroll
            for (int i = 0; i < TM; i++) a[i] = As[k][ty * TM + i];
            #pragma unroll
            for (int j = 0; j < TN; j++) b[j] = Bs[k][tx * TN + j];
            #pragma unroll
            for (int i = 0; i < TM; i++)
                #pragma unroll
                for (int j = 0; j < TN; j++)
                    acc[i][j] = fmaf(a[i], b[j], acc[i][j]);
        }
        __syncthreads();
    }

    const float cc     = fmaxf(cptr[0], EPSF);
    const float isc    = rsqrtf(cc);
    const float two_cc = 2.0f * cc;

    // compute dist values in-place in acc
    #pragma unroll
    for (int i = 0; i < TM; i++) {
        int m = m0 + ty * TM + i;
        float nm  = norm[m];
        float rtm = rterm[m];
        #pragma unroll
        for (int j = 0; j < TN; j++) {
            int n = n0 + tx * TN + j;
            float g   = acc[i][j];
            float d2  = fmaxf(nm + norm[n] - 2.0f * g, 0.0f);
            float arg = fmaf(two_cc * d2, rtm * rterm[n], 1.0f);
            arg = fmaxf(arg, 1.0f + EPSF) + EPSF;
            float ach = __logf(arg + __fsqrt_rn(fmaf(arg, arg, -1.0f)));
            acc[i][j] = -ach * isc;
        }
    }

    // normal store (coalesced): S[m][n]
    #pragma unroll
    for (int i = 0; i < TM; i++) {
        int m = m0 + ty * TM + i;
        float4* dst = reinterpret_cast<float4*>(&S[(size_t)m * N + n0 + tx * TN]);
        dst[0] = make_float4(acc[i][0], acc[i][1], acc[i][2], acc[i][3]);
        dst[1] = make_float4(acc[i][4], acc[i][5], acc[i][6], acc[i][7]);
    }

    // mirrored store: S[n][m] (skip on diagonal blocks; values identical)
    if (bm != bn) {
        #pragma unroll
        for (int j = 0; j < TN; j++) {
            int n = n0 + tx * TN + j;
            float4* dst = reinterpret_cast<float4*>(&S[(size_t)n * N + m0 + ty * TM]);
            dst[0] = make_float4(acc[0][j], acc[1][j], acc[2][j], acc[3][j]);
            dst[1] = make_float4(acc[4][j], acc[5][j], acc[6][j], acc[7][j]);
        }
    }
}

// ------------------------- row squared norms + 1/term -------------------------
__global__ void row_norms(const float* __restrict__ X, float* __restrict__ norm,
                          float* __restrict__ rterm,
                          const float* __restrict__ cptr, int B, int D)
{
    int warp = (blockIdx.x * blockDim.x + threadIdx.x) >> 5;
    int lane = threadIdx.x & 31;
    if (warp >= B) return;
    const float* x = X + (size_t)warp * D;
    float s = 0.0f;
    for (int k = lane; k < D; k += 32) { float v = x[k]; s = fmaf(v, v, s); }
    #pragma unroll
    for (int o = 16; o; o >>= 1) s += __shfl_xor_sync(0xFFFFFFFFu, s, o);
    if (lane == 0) {
        norm[warp] = s;
        float cc = fmaxf(cptr[0], EPSF);
        float t  = fmaxf(1.0f - cc * s, EPSF);
        rterm[warp] = 1.0f / t;
    }
}

// ------------------------- row softmax + sparsity compaction -------------------------
__global__ void __launch_bounds__(256)
softmax_compact(const float* __restrict__ S, int* __restrict__ spi,
                float* __restrict__ spv, int* __restrict__ cnt, int N)
{
    __shared__ float buf[BATCH];
    __shared__ float red[32];
    __shared__ int   wbase[8];
    const int tid = threadIdx.x;
    const int row = blockIdx.x;
    const float* Sr = S + (size_t)row * N;

    // --- max ---
    float mx = -3.4e38f;
    for (int i = tid; i < N; i += 256) { float v = Sr[i]; buf[i] = v; mx = fmaxf(mx, v); }
    #pragma unroll
    for (int o = 16; o; o >>= 1) mx = fmaxf(mx, __shfl_xor_sync(0xFFFFFFFFu, mx, o));
    if ((tid & 31) == 0) red[tid >> 5] = mx;
    __syncthreads();
    if (tid < 32) {
        float v = (tid < 8) ? red[tid] : -3.4e38f;
        #pragma unroll
        for (int o = 4; o; o >>= 1) v = fmaxf(v, __shfl_xor_sync(0xFFFFFFFFu, v, o));
        if (tid == 0) red[0] = v;
    }
    __syncthreads();
    mx = red[0];

    // --- exp & sum ---
    float sum = 0.0f;
    for (int i = tid; i < N; i += 256) { float e = __expf(buf[i] - mx); buf[i] = e; sum += e; }
    __syncthreads();
    #pragma unroll
    for (int o = 16; o; o >>= 1) sum += __shfl_xor_sync(0xFFFFFFFFu, sum, o);
    if ((tid & 31) == 0) red[tid >> 5] = sum;
    __syncthreads();
    if (tid < 32) {
        float v = (tid < 8) ? red[tid] : 0.0f;
        #pragma unroll
        for (int o = 4; o; o >>= 1) v += __shfl_xor_sync(0xFFFFFFFFu, v, o);
        if (tid == 0) red[0] = v;
    }
    __syncthreads();
    const float inv = 1.0f / red[0];

    // --- count surviving entries per thread ---
    int c = 0;
    for (int i = tid; i < N; i += 256)
        if (buf[i] * inv >= P_THRESH) c++;

    // --- deterministic exclusive scan over 256 threads ---
    int lane = tid & 31, w = tid >> 5;
    int incl = c;
    #pragma unroll
    for (int o = 1; o < 32; o <<= 1) {
        int t = __shfl_up_sync(0xFFFFFFFFu, incl, o);
        if (lane >= o) incl += t;
    }
    if (lane == 31) wbase[w] = incl;
    __syncthreads();
    if (tid == 0) {
        int s = 0;
        #pragma unroll
        for (int k = 0; k < 8; k++) { int t = wbase[k]; wbase[k] = s; s += t; }
        cnt[row] = s;
    }
    __syncthreads();
    int pos = wbase[w] + incl - c;

    // --- write compacted (idx, val) ---
    for (int i = tid; i < N; i += 256) {
        float p = buf[i] * inv;
        if (p >= P_THRESH) {
            spi[(size_t)row * N + pos] = i;
            spv[(size_t)row * N + pos] = p;
            pos++;
        }
    }
}

// ------------------------- sparse attn: attn[r,:] = sum_t val_t * corr[idx_t,:] -------------------------
__global__ void __launch_bounds__(256)
attn_sparse(const int* __restrict__ spi, const float* __restrict__ spv,
            const int* __restrict__ cnt, const float* __restrict__ corr,
            float* __restrict__ attn)
{
    const int row = blockIdx.x;
    const int tid = threadIdx.x;
    const int n = cnt[row];
    const float4* corr4 = reinterpret_cast<const float4*>(corr);
    float4 acc = make_float4(0.f, 0.f, 0.f, 0.f);
    for (int t = 0; t < n; t++) {
        int   idx = spi[(size_t)row * BATCH + t];
        float v   = spv[(size_t)row * BATCH + t];
        float4 x  = corr4[(size_t)idx * (HIDDIM / 4) + tid];
        acc.x = fmaf(v, x.x, acc.x);
        acc.y = fmaf(v, x.y, acc.y);
        acc.z = fmaf(v, x.z, acc.z);
        acc.w = fmaf(v, x.w, acc.w);
    }
    reinterpret_cast<float4*>(attn)[(size_t)row * (HIDDIM / 4) + tid] = acc;
}

// ------------------------- heads epilogue: softmax(64) + risk sigmoid -------------------------
__global__ void heads_epilogue(const float* __restrict__ logits,
                               const float* __restrict__ attn,
                               const float* __restrict__ W_risk,
                               const float* __restrict__ b_risk,
                               float* __restrict__ probs,
                               float* __restrict__ risk,
                               int B, int D)
{
    int warp = (blockIdx.x * blockDim.x + threadIdx.x) >> 5;
    int lane = threadIdx.x & 31;
    if (warp >= B) return;

    const float* ar = attn + (size_t)warp * D;
    float s = 0.0f;
    for (int k = lane; k < D; k += 32) s = fmaf(ar[k], W_risk[k], s);
    #pragma unroll
    for (int o = 16; o; o >>= 1) s += __shfl_xor_sync(0xFFFFFFFFu, s, o);
    if (lane == 0) risk[warp] = 1.0f / (1.0f + expf(-(s + b_risk[0])));

    const float* lr = logits + (size_t)warp * ACTDIM;
    float v0 = lr[lane], v1 = lr[lane + 32];
    float mx = fmaxf(v0, v1);
    #pragma unroll
    for (int o = 16; o; o >>= 1) mx = fmaxf(mx, __shfl_xor_sync(0xFFFFFFFFu, mx, o));
    float e0 = expf(v0 - mx), e1 = expf(v1 - mx);
    float ss = e0 + e1;
    #pragma unroll
    for (int o = 16; o; o >>= 1) ss += __shfl_xor_sync(0xFFFFFFFFu, ss, o);
    float inv = 1.0f / ss;
    probs[(size_t)warp * ACTDIM + lane]      = e0 * inv;
    probs[(size_t)warp * ACTDIM + lane + 32] = e1 * inv;
}

// ------------------------- launch -------------------------
extern "C" void kernel_launch(void* const* d_in, const int* in_sizes, int n_in,
                              void* d_out, int out_size)
{
    const float* state   = (const float*)d_in[0];
    const float* W_enc   = (const float*)d_in[1];
    const float* b_enc   = (const float*)d_in[2];
    const float* cov     = (const float*)d_in[3];
    const float* W_phase = (const float*)d_in[4];
    const float* b_phase = (const float*)d_in[5];
    const float* cptr    = (const float*)d_in[6];
    const float* W_actor = (const float*)d_in[7];
    const float* b_actor = (const float*)d_in[8];
    const float* W_risk  = (const float*)d_in[9];
    const float* b_risk  = (const float*)d_in[10];

    float* out    = (float*)d_out;
    float* logits = out;                                    // [B, 64]
    float* probs  = out + (size_t)BATCH * ACTDIM;           // [B, 64]
    float* risk   = out + (size_t)2 * BATCH * ACTDIM;       // [B, 1]

    float *enc, *t1, *corr, *attn, *nrm, *rterm, *S, *spv;
    int *spi, *cnt;
    cudaGetSymbolAddress((void**)&enc,   g_enc);
    cudaGetSymbolAddress((void**)&t1,    g_t1);
    cudaGetSymbolAddress((void**)&corr,  g_corr);
    cudaGetSymbolAddress((void**)&attn,  g_attn);
    cudaGetSymbolAddress((void**)&nrm,   g_norm);
    cudaGetSymbolAddress((void**)&rterm, g_rterm);
    cudaGetSymbolAddress((void**)&S,     g_S);
    cudaGetSymbolAddress((void**)&spi,   g_spi);
    cudaGetSymbolAddress((void**)&spv,   g_spv);
    cudaGetSymbolAddress((void**)&cnt,   g_cnt);

    // 1) enc = relu(state @ W_enc + b_enc)   [8192,512]x[512,1024]
    gemm_nn<128,128,16,8,8,1><<<dim3(HIDDIM/128, BATCH/128), 256>>>(
        state, W_enc, enc, BATCH, HIDDIM, INDIM, b_enc, nullptr);

    // 2) t1 = enc @ cov   [8192,1024]x[1024,1024]
    gemm_nn<128,128,16,8,8,0><<<dim3(HIDDIM/128, BATCH/128), 256>>>(
        enc, cov, t1, BATCH, HIDDIM, HIDDIM, nullptr, nullptr);

    // 3) corr = tanh(t1 @ W_phase + b_phase) + enc
    gemm_nn<128,128,16,8,8,2><<<dim3(HIDDIM/128, BATCH/128), 256>>>(
        t1, W_phase, corr, BATCH, HIDDIM, HIDDIM, b_phase, enc);

    // 4) per-row squared norms + 1/term
    row_norms<<<BATCH/8, 256>>>(corr, nrm, rterm, cptr, BATCH, HIDDIM);

    // 5) S = -dist(corr, corr), upper-triangular blocks only + mirror store
    gemm_nt_dist_sym<128,128,16,8,8><<<NBLK * (NBLK + 1) / 2, 256>>>(
        corr, S, BATCH, HIDDIM, nrm, rterm, cptr);

    // 6) softmax rows + sparsity compaction (no dense P written)
    softmax_compact<<<BATCH, 256>>>(S, spi, spv, cnt, BATCH);

    // 7) attn = P @ corr, exploiting bounded-error sparsity of P
    attn_sparse<<<BATCH, 256>>>(spi, spv, cnt, corr, attn);

    // 8) logits = attn @ W_actor + b_actor  -> directly into out
    gemm_nn<128,64,16,8,4,3><<<dim3(ACTDIM/64, BATCH/128), 256>>>(
        attn, W_actor, logits, BATCH, ACTDIM, HIDDIM, b_actor, nullptr);

    // 9) probs + risk
    heads_epilogue<<<BATCH/8, 256>>>(logits, attn, W_risk, b_risk, probs, risk, BATCH, HIDDIM);
}

// round 9
// speedup vs baseline: 4.7544x; 1.5314x over previous
#include <cuda_runtime.h>
#include <cuda_bf16.h>
#include <mma.h>
#include <math.h>

using namespace nvcuda;

#define EPSF 1e-6f

#define BATCH 8192
#define INDIM 512
#define HIDDIM 1024
#define ACTDIM 64

// Sparsity threshold for softmax weights. Dropped probability mass per row is
// bounded by 8192 * 1e-9 = 8.2e-6 -> |attn error| ~ 2e-5 absolute, two orders
// below the 1e-3 correctness gate. Input-independent bound.
#define P_THRESH 1e-9f

// Number of 128-wide block-rows/cols in the S matrix
#define NBLK (BATCH / 128)

// ------------------------- scratch (no cudaMalloc allowed) -------------------------
__device__ float          g_enc  [(size_t)BATCH * HIDDIM];
__device__ float          g_t1   [(size_t)BATCH * HIDDIM];
__device__ float          g_corr [(size_t)BATCH * HIDDIM];
__device__ __nv_bfloat16  g_corrb[(size_t)BATCH * HIDDIM];
__device__ float          g_attn [(size_t)BATCH * HIDDIM];
__device__ float          g_norm [BATCH];
__device__ float          g_rterm[BATCH];
__device__ float          g_S    [(size_t)BATCH * BATCH];
__device__ int            g_spi  [(size_t)BATCH * BATCH];
__device__ float          g_spv  [(size_t)BATCH * BATCH];
__device__ int            g_cnt  [BATCH];

// ------------------------- generic NN GEMM with epilogues (scalar FFMA) -------------------------
// C[M,N] = epi(A[M,K] @ B[K,N])
// EPI: 0 = none, 1 = relu(x + bias[n]), 2 = tanh(x + bias[n]) + extra[m,n], 3 = x + bias[n]
template<int BM, int BN, int BK, int TM, int TN, int EPI>
__global__ void __launch_bounds__(256)
gemm_nn(const float* __restrict__ A, const float* __restrict__ B,
        float* __restrict__ C, int M, int N, int K,
        const float* __restrict__ bias, const float* __restrict__ extra)
{
    __shared__ float As[BK][BM + 4];
    __shared__ float Bs[BK][BN + 4];

    const int tid = threadIdx.x;
    const int m0 = blockIdx.y * BM;
    const int n0 = blockIdx.x * BN;
    constexpr int TX = BN / TN;
    const int tx = tid % TX;
    const int ty = tid / TX;

    float acc[TM][TN] = {};

    constexpr int LA = BM * BK / (4 * 256);
    constexpr int LB = BK * BN / (4 * 256);

    for (int k0 = 0; k0 < K; k0 += BK) {
        #pragma unroll
        for (int i = 0; i < LA; i++) {
            int f4  = tid + i * 256;
            int row = f4 / (BK / 4);
            int c4  = f4 % (BK / 4);
            float4 v = *reinterpret_cast<const float4*>(&A[(size_t)(m0 + row) * K + k0 + c4 * 4]);
            As[c4 * 4 + 0][row] = v.x;
            As[c4 * 4 + 1][row] = v.y;
            As[c4 * 4 + 2][row] = v.z;
            As[c4 * 4 + 3][row] = v.w;
        }
        #pragma unroll
        for (int i = 0; i < LB; i++) {
            int f4  = tid + i * 256;
            int row = f4 / (BN / 4);
            int c4  = f4 % (BN / 4);
            float4 v = *reinterpret_cast<const float4*>(&B[(size_t)(k0 + row) * N + n0 + c4 * 4]);
            *reinterpret_cast<float4*>(&Bs[row][c4 * 4]) = v;
        }
        __syncthreads();

        #pragma unroll
        for (int k = 0; k < BK; k++) {
            float a[TM], b[TN];
            #pragma unroll
            for (int i = 0; i < TM; i++) a[i] = As[k][ty * TM + i];
            #pragma unroll
            for (int j = 0; j < TN; j++) b[j] = Bs[k][tx * TN + j];
            #pragma unroll
            for (int i = 0; i < TM; i++)
                #pragma unroll
                for (int j = 0; j < TN; j++)
                    acc[i][j] = fmaf(a[i], b[j], acc[i][j]);
        }
        __syncthreads();
    }

    #pragma unroll
    for (int i = 0; i < TM; i++) {
        int m = m0 + ty * TM + i;
        #pragma unroll
        for (int j = 0; j < TN; j++) {
            int n = n0 + tx * TN + j;
            float v = acc[i][j];
            if constexpr (EPI == 1) v = fmaxf(v + bias[n], 0.0f);
            if constexpr (EPI == 2) v = tanhf(v + bias[n]) + extra[(size_t)m * N + n];
            if constexpr (EPI == 3) v = v + bias[n];
            C[(size_t)m * N + n] = v;
        }
    }
}

// ------------------------- fp32 -> bf16 conversion -------------------------
__global__ void to_bf16(const float* __restrict__ x, __nv_bfloat16* __restrict__ y)
{
    size_t i = ((size_t)blockIdx.x * blockDim.x + threadIdx.x) * 4;
    float4 v = *reinterpret_cast<const float4*>(&x[i]);
    __nv_bfloat162 lo = __floats2bfloat162_rn(v.x, v.y);
    __nv_bfloat162 hi = __floats2bfloat162_rn(v.z, v.w);
    *reinterpret_cast<__nv_bfloat162*>(&y[i])     = lo;
    *reinterpret_cast<__nv_bfloat162*>(&y[i + 2]) = hi;
}

// ------------------------- symmetric Gram via bf16 HMMA + hyperbolic-distance epilogue -------------------------
// Upper-triangular 128x128 blocks only; off-diagonal blocks also store the
// mirrored tile. Mainloop: wmma m16n16k16 bf16 -> fp32. Raw Gram values are
// staged in the S tile itself, then an epilogue pass converts in place.
// d2(m,m) is set to exactly 0 (mathematical identity), making the diagonal
// the exact row max regardless of bf16 rounding.
#define GBK 64
#define GPAD 8
__global__ void __launch_bounds__(256)
gram_dist_wmma(const __nv_bfloat16* __restrict__ Abf, float* __restrict__ S,
               int N, int K,
               const float* __restrict__ norm, const float* __restrict__ rterm,
               const float* __restrict__ cptr)
{
    // --- triangular block decode: blockIdx.x -> (bm, bn), bm <= bn ---
    const int t = blockIdx.x;
    int bm = (int)(((2.0f * NBLK + 1.0f) -
                    sqrtf((float)((2 * NBLK + 1) * (2 * NBLK + 1) - 8 * t))) * 0.5f);
    if (bm < 0) bm = 0;
    if (bm >= NBLK) bm = NBLK - 1;
    #pragma unroll 1
    while (bm + 1 < NBLK && ((bm + 1) * NBLK - (bm * (bm + 1)) / 2) <= t) bm++;
    #pragma unroll 1
    while (bm > 0 && (bm * NBLK - ((bm - 1) * bm) / 2) > t) bm--;
    const int bn = bm + (t - (bm * NBLK - ((bm - 1) * bm) / 2));

    const int m0 = bm * 128;
    const int n0 = bn * 128;

    __shared__ __nv_bfloat16 As[128][GBK + GPAD];
    __shared__ __nv_bfloat16 Bs[128][GBK + GPAD];

    const int tid = threadIdx.x;
    const int wid = tid >> 5;
    const int warp_m = wid & 1;    // 2 warps along m -> 64 rows each
    const int warp_n = wid >> 1;   // 4 warps along n -> 32 cols each

    wmma::fragment<wmma::accumulator, 16, 16, 16, float> cf[4][2];
    #pragma unroll
    for (int i = 0; i < 4; i++)
        #pragma unroll
        for (int j = 0; j < 2; j++)
            wmma::fill_fragment(cf[i][j], 0.0f);

    for (int k0 = 0; k0 < K; k0 += GBK) {
        // load A tile: 128 rows x 64 bf16 (uint4 = 8 bf16 per load)
        #pragma unroll
        for (int i = 0; i < 4; i++) {
            int idx = tid + i * 256;
            int row = idx >> 3;
            int g   = idx & 7;
            *reinterpret_cast<uint4*>(&As[row][g * 8]) =
                *reinterpret_cast<const uint4*>(&Abf[(size_t)(m0 + row) * K + k0 + g * 8]);
        }
        #pragma unroll
        for (int i = 0; i < 4; i++) {
            int idx = tid + i * 256;
            int row = idx >> 3;
            int g   = idx & 7;
            *reinterpret_cast<uint4*>(&Bs[row][g * 8]) =
                *reinterpret_cast<const uint4*>(&Abf[(size_t)(n0 + row) * K + k0 + g * 8]);
        }
        __syncthreads();

        #pragma unroll
        for (int ks = 0; ks < GBK; ks += 16) {
            wmma::fragment<wmma::matrix_a, 16, 16, 16, __nv_bfloat16, wmma::row_major> af[4];
            wmma::fragment<wmma::matrix_b, 16, 16, 16, __nv_bfloat16, wmma::col_major> bf[2];
            #pragma unroll
            for (int i = 0; i < 4; i++)
                wmma::load_matrix_sync(af[i], &As[warp_m * 64 + i * 16][ks], GBK + GPAD);
            #pragma unroll
            for (int j = 0; j < 2; j++)
                wmma::load_matrix_sync(bf[j], &Bs[warp_n * 32 + j * 16][ks], GBK + GPAD);
            #pragma unroll
            for (int i = 0; i < 4; i++)
                #pragma unroll
                for (int j = 0; j < 2; j++)
                    wmma::mma_sync(cf[i][j], af[i], bf[j], cf[i][j]);
        }
        __syncthreads();
    }

    // stage raw Gram values into the S tile
    #pragma unroll
    for (int i = 0; i < 4; i++) {
        #pragma unroll
        for (int j = 0; j < 2; j++) {
            int m = m0 + warp_m * 64 + i * 16;
            int n = n0 + warp_n * 32 + j * 16;
            wmma::store_matrix_sync(&S[(size_t)m * N + n], cf[i][j], N, wmma::mem_row_major);
        }
    }
    __syncthreads();   // block-scope visibility of global writes

    // epilogue: read raw g, write dist to S[m][n] and mirror S[n][m]
    const float cc     = fmaxf(cptr[0], EPSF);
    const float isc    = rsqrtf(cc);
    const float two_cc = 2.0f * cc;
    const bool  diag   = (bm == bn);

    for (int idx = tid; idx < 128 * 128; idx += 256) {
        int i = idx >> 7, j = idx & 127;
        if (diag && j < i) continue;          // mirrored partner handles nothing; skip lower half
        int m = m0 + i, n = n0 + j;
        float g  = S[(size_t)m * N + n];
        float d2 = (m == n) ? 0.0f : fmaxf(norm[m] + norm[n] - 2.0f * g, 0.0f);
        float arg = fmaf(two_cc * d2, rterm[m] * rterm[n], 1.0f);
        arg = fmaxf(arg, 1.0f + EPSF) + EPSF;
        float v = -__logf(arg + __fsqrt_rn(fmaf(arg, arg, -1.0f))) * isc;
        S[(size_t)m * N + n] = v;
        if (m != n) S[(size_t)n * N + m] = v;
    }
}

// ------------------------- row squared norms + 1/term -------------------------
__global__ void row_norms(const float* __restrict__ X, float* __restrict__ norm,
                          float* __restrict__ rterm,
                          const float* __restrict__ cptr, int B, int D)
{
    int warp = (blockIdx.x * blockDim.x + threadIdx.x) >> 5;
    int lane = threadIdx.x & 31;
    if (warp >= B) return;
    const float* x = X + (size_t)warp * D;
    float s = 0.0f;
    for (int k = lane; k < D; k += 32) { float v = x[k]; s = fmaf(v, v, s); }
    #pragma unroll
    for (int o = 16; o; o >>= 1) s += __shfl_xor_sync(0xFFFFFFFFu, s, o);
    if (lane == 0) {
        norm[warp] = s;
        float cc = fmaxf(cptr[0], EPSF);
        float t  = fmaxf(1.0f - cc * s, EPSF);
        rterm[warp] = 1.0f / t;
    }
}

// ------------------------- row softmax + sparsity compaction -------------------------
__global__ void __launch_bounds__(256)
softmax_compact(const float* __restrict__ S, int* __restrict__ spi,
                float* __restrict__ spv, int* __restrict__ cnt, int N)
{
    __shared__ float buf[BATCH];
    __shared__ float red[32];
    __shared__ int   wbase[8];
    const int tid = threadIdx.x;
    const int row = blockIdx.x;
    const float* Sr = S + (size_t)row * N;

    // --- max ---
    float mx = -3.4e38f;
    for (int i = tid; i < N; i += 256) { float v = Sr[i]; buf[i] = v; mx = fmaxf(mx, v); }
    #pragma unroll
    for (int o = 16; o; o >>= 1) mx = fmaxf(mx, __shfl_xor_sync(0xFFFFFFFFu, mx, o));
    if ((tid & 31) == 0) red[tid >> 5] = mx;
    __syncthreads();
    if (tid < 32) {
        float v = (tid < 8) ? red[tid] : -3.4e38f;
        #pragma unroll
        for (int o = 4; o; o >>= 1) v = fmaxf(v, __shfl_xor_sync(0xFFFFFFFFu, v, o));
        if (tid == 0) red[0] = v;
    }
    __syncthreads();
    mx = red[0];

    // --- exp & sum ---
    float sum = 0.0f;
    for (int i = tid; i < N; i += 256) { float e = __expf(buf[i] - mx); buf[i] = e; sum += e; }
    __syncthreads();
    #pragma unroll
    for (int o = 16; o; o >>= 1) sum += __shfl_xor_sync(0xFFFFFFFFu, sum, o);
    if ((tid & 31) == 0) red[tid >> 5] = sum;
    __syncthreads();
    if (tid < 32) {
        float v = (tid < 8) ? red[tid] : 0.0f;
        #pragma unroll
        for (int o = 4; o; o >>= 1) v += __shfl_xor_sync(0xFFFFFFFFu, v, o);
        if (tid == 0) red[0] = v;
    }
    __syncthreads();
    const float inv = 1.0f / red[0];

    // --- count surviving entries per thread ---
    int c = 0;
    for (int i = tid; i < N; i += 256)
        if (buf[i] * inv >= P_THRESH) c++;

    // --- deterministic exclusive scan over 256 threads ---
    int lane = tid & 31, w = tid >> 5;
    int incl = c;
    #pragma unroll
    for (int o = 1; o < 32; o <<= 1) {
        int t = __shfl_up_sync(0xFFFFFFFFu, incl, o);
        if (lane >= o) incl += t;
    }
    if (lane == 31) wbase[w] = incl;
    __syncthreads();
    if (tid == 0) {
        int s = 0;
        #pragma unroll
        for (int k = 0; k < 8; k++) { int t = wbase[k]; wbase[k] = s; s += t; }
        cnt[row] = s;
    }
    __syncthreads();
    int pos = wbase[w] + incl - c;

    // --- write compacted (idx, val) ---
    for (int i = tid; i < N; i += 256) {
        float p = buf[i] * inv;
        if (p >= P_THRESH) {
            spi[(size_t)row * N + pos] = i;
            spv[(size_t)row * N + pos] = p;
            pos++;
        }
    }
}

// ------------------------- sparse attn: attn[r,:] = sum_t val_t * corr[idx_t,:] -------------------------
__global__ void __launch_bounds__(256)
attn_sparse(const int* __restrict__ spi, const float* __restrict__ spv,
            const int* __restrict__ cnt, const float* __restrict__ corr,
            float* __restrict__ attn)
{
    const int row = blockIdx.x;
    const int tid = threadIdx.x;
    const int n = cnt[row];
    const float4* corr4 = reinterpret_cast<const float4*>(corr);
    float4 acc = make_float4(0.f, 0.f, 0.f, 0.f);
    for (int t = 0; t < n; t++) {
        int   idx = spi[(size_t)row * BATCH + t];
        float v   = spv[(size_t)row * BATCH + t];
        float4 x  = corr4[(size_t)idx * (HIDDIM / 4) + tid];
        acc.x = fmaf(v, x.x, acc.x);
        acc.y = fmaf(v, x.y, acc.y);
        acc.z = fmaf(v, x.z, acc.z);
        acc.w = fmaf(v, x.w, acc.w);
    }
    reinterpret_cast<float4*>(attn)[(size_t)row * (HIDDIM / 4) + tid] = acc;
}

// ------------------------- heads epilogue: softmax(64) + risk sigmoid -------------------------
__global__ void heads_epilogue(const float* __restrict__ logits,
                               const float* __restrict__ attn,
                               const float* __restrict__ W_risk,
                               const float* __restrict__ b_risk,
                               float* __restrict__ probs,
                               float* __restrict__ risk,
                               int B, int D)
{
    int warp = (blockIdx.x * blockDim.x + threadIdx.x) >> 5;
    int lane = threadIdx.x & 31;
    if (warp >= B) return;

    const float* ar = attn + (size_t)warp * D;
    float s = 0.0f;
    for (int k = lane; k < D; k += 32) s = fmaf(ar[k], W_risk[k], s);
    #pragma unroll
    for (int o = 16; o; o >>= 1) s += __shfl_xor_sync(0xFFFFFFFFu, s, o);
    if (lane == 0) risk[warp] = 1.0f / (1.0f + expf(-(s + b_risk[0])));

    const float* lr = logits + (size_t)warp * ACTDIM;
    float v0 = lr[lane], v1 = lr[lane + 32];
    float mx = fmaxf(v0, v1);
    #pragma unroll
    for (int o = 16; o; o >>= 1) mx = fmaxf(mx, __shfl_xor_sync(0xFFFFFFFFu, mx, o));
    float e0 = expf(v0 - mx), e1 = expf(v1 - mx);
    float ss = e0 + e1;
    #pragma unroll
    for (int o = 16; o; o >>= 1) ss += __shfl_xor_sync(0xFFFFFFFFu, ss, o);
    float inv = 1.0f / ss;
    probs[(size_t)warp * ACTDIM + lane]      = e0 * inv;
    probs[(size_t)warp * ACTDIM + lane + 32] = e1 * inv;
}

// ------------------------- launch -------------------------
extern "C" void kernel_launch(void* const* d_in, const int* in_sizes, int n_in,
                              void* d_out, int out_size)
{
    const float* state   = (const float*)d_in[0];
    const float* W_enc   = (const float*)d_in[1];
    const float* b_enc   = (const float*)d_in[2];
    const float* cov     = (const float*)d_in[3];
    const float* W_phase = (const float*)d_in[4];
    const float* b_phase = (const float*)d_in[5];
    const float* cptr    = (const float*)d_in[6];
    const float* W_actor = (const float*)d_in[7];
    const float* b_actor = (const float*)d_in[8];
    const float* W_risk  = (const float*)d_in[9];
    const float* b_risk  = (const float*)d_in[10];

    float* out    = (float*)d_out;
    float* logits = out;                                    // [B, 64]
    float* probs  = out + (size_t)BATCH * ACTDIM;           // [B, 64]
    float* risk   = out + (size_t)2 * BATCH * ACTDIM;       // [B, 1]

    float *enc, *t1, *corr, *attn, *nrm, *rterm, *S, *spv;
    __nv_bfloat16* corrb;
    int *spi, *cnt;
    cudaGetSymbolAddress((void**)&enc,   g_enc);
    cudaGetSymbolAddress((void**)&t1,    g_t1);
    cudaGetSymbolAddress((void**)&corr,  g_corr);
    cudaGetSymbolAddress((void**)&corrb, g_corrb);
    cudaGetSymbolAddress((void**)&attn,  g_attn);
    cudaGetSymbolAddress((void**)&nrm,   g_norm);
    cudaGetSymbolAddress((void**)&rterm, g_rterm);
    cudaGetSymbolAddress((void**)&S,     g_S);
    cudaGetSymbolAddress((void**)&spi,   g_spi);
    cudaGetSymbolAddress((void**)&spv,   g_spv);
    cudaGetSymbolAddress((void**)&cnt,   g_cnt);

    // 1) enc = relu(state @ W_enc + b_enc)   [8192,512]x[512,1024]
    gemm_nn<128,128,16,8,8,1><<<dim3(HIDDIM/128, BATCH/128), 256>>>(
        state, W_enc, enc, BATCH, HIDDIM, INDIM, b_enc, nullptr);

    // 2) t1 = enc @ cov   [8192,1024]x[1024,1024]
    gemm_nn<128,128,16,8,8,0><<<dim3(HIDDIM/128, BATCH/128), 256>>>(
        enc, cov, t1, BATCH, HIDDIM, HIDDIM, nullptr, nullptr);

    // 3) corr = tanh(t1 @ W_phase + b_phase) + enc
    gemm_nn<128,128,16,8,8,2><<<dim3(HIDDIM/128, BATCH/128), 256>>>(
        t1, W_phase, corr, BATCH, HIDDIM, HIDDIM, b_phase, enc);

    // 4) per-row squared norms + 1/term  ;  bf16 copy of corr for the tensor-core Gram
    row_norms<<<BATCH/8, 256>>>(corr, nrm, rterm, cptr, BATCH, HIDDIM);
    to_bf16<<<(BATCH * HIDDIM) / (4 * 256), 256>>>(corr, corrb);

    // 5) S = -dist(corr, corr): bf16 HMMA Gram, upper-tri blocks + mirror store
    gram_dist_wmma<<<NBLK * (NBLK + 1) / 2, 256>>>(
        corrb, S, BATCH, HIDDIM, nrm, rterm, cptr);

    // 6) softmax rows + sparsity compaction (no dense P written)
    softmax_compact<<<BATCH, 256>>>(S, spi, spv, cnt, BATCH);

    // 7) attn = P @ corr, exploiting bounded-error sparsity of P
    attn_sparse<<<BATCH, 256>>>(spi, spv, cnt, corr, attn);

    // 8) logits = attn @ W_actor + b_actor  -> directly into out
    gemm_nn<128,64,16,8,4,3><<<dim3(ACTDIM/64, BATCH/128), 256>>>(
        attn, W_actor, logits, BATCH, ACTDIM, HIDDIM, b_actor, nullptr);

    // 9) probs + risk
    heads_epilogue<<<BATCH/8, 256>>>(logits, attn, W_risk, b_risk, probs, risk, BATCH, HIDDIM);
}

// round 13
// speedup vs baseline: 6.1960x; 1.3032x over previous
#include <cuda_runtime.h>
#include <cuda_bf16.h>
#include <mma.h>
#include <math.h>

using namespace nvcuda;

#define EPSF 1e-6f

#define BATCH 8192
#define INDIM 512
#define HIDDIM 1024
#define ACTDIM 64

// Sparsity threshold for softmax weights. Dropped probability mass per row is
// bounded by 8192 * 1e-9 = 8.2e-6 -> |attn error| ~ 2e-5 absolute, two orders
// below the 1e-3 correctness gate. Input-independent bound.
#define P_THRESH 1e-9f

#define NBLK (BATCH / 128)

// ------------------------- scratch (no cudaMalloc allowed) -------------------------
__device__ float          g_enc  [(size_t)BATCH * HIDDIM];
__device__ float          g_corr [(size_t)BATCH * HIDDIM];
__device__ __nv_bfloat16  g_corrb[(size_t)BATCH * HIDDIM];
__device__ float          g_attn [(size_t)BATCH * HIDDIM];
__device__ float          g_norm [BATCH];
__device__ float          g_rterm[BATCH];
__device__ float          g_S    [(size_t)BATCH * BATCH];
__device__ int            g_spi  [(size_t)BATCH * BATCH];
__device__ float          g_spv  [(size_t)BATCH * BATCH];
__device__ int            g_cnt  [BATCH];

// split-bf16 operands (hi/lo pairs)
__device__ __nv_bfloat16  g_state_h[(size_t)BATCH * INDIM];
__device__ __nv_bfloat16  g_state_l[(size_t)BATCH * INDIM];
__device__ __nv_bfloat16  g_Wenc_h [(size_t)INDIM * HIDDIM];
__device__ __nv_bfloat16  g_Wenc_l [(size_t)INDIM * HIDDIM];
__device__ __nv_bfloat16  g_cov_h  [(size_t)HIDDIM * HIDDIM];
__device__ __nv_bfloat16  g_cov_l  [(size_t)HIDDIM * HIDDIM];
__device__ __nv_bfloat16  g_Wph_h  [(size_t)HIDDIM * HIDDIM];
__device__ __nv_bfloat16  g_Wph_l  [(size_t)HIDDIM * HIDDIM];
__device__ __nv_bfloat16  g_enc_h  [(size_t)BATCH * HIDDIM];
__device__ __nv_bfloat16  g_enc_l  [(size_t)BATCH * HIDDIM];
__device__ __nv_bfloat16  g_t1_h   [(size_t)BATCH * HIDDIM];
__device__ __nv_bfloat16  g_t1_l   [(size_t)BATCH * HIDDIM];

// ------------------------- fp32 -> (hi, lo) bf16 split -------------------------
__global__ void split_bf16(const float* __restrict__ x,
                           __nv_bfloat16* __restrict__ h,
                           __nv_bfloat16* __restrict__ l)
{
    size_t i = ((size_t)blockIdx.x * blockDim.x + threadIdx.x) * 4;
    float4 v = *reinterpret_cast<const float4*>(&x[i]);
    __nv_bfloat16 hv[4], lv[4];
    float vv[4] = {v.x, v.y, v.z, v.w};
    #pragma unroll
    for (int t = 0; t < 4; t++) {
        hv[t] = __float2bfloat16_rn(vv[t]);
        lv[t] = __float2bfloat16_rn(vv[t] - __bfloat162float(hv[t]));
    }
    *reinterpret_cast<uint2*>(&h[i]) = *reinterpret_cast<uint2*>(hv);
    *reinterpret_cast<uint2*>(&l[i]) = *reinterpret_cast<uint2*>(lv);
}

// ------------------------- split-bf16 wmma GEMM with fused epilogues -------------------------
// C = epi(A @ B) where A = Ah + Al, B = Bh + Bl (bf16 splits of fp32 matrices).
// Computes ah*bh + al*bh + ah*bl in fp32 accumulators (drops al*bl <= 2^-16 rel).
// SEPI 1: v = relu(acc + bias[n]); write Cf (fp32) + Ch/Cl (bf16 split of v)
// SEPI 0: v = acc;                 write Ch/Cl only
// SEPI 2: v = tanh(acc + bias[n]) + extra[m,n]; write Cf + Ch (single bf16)
template<int SEPI>
__global__ void __launch_bounds__(256)
gemm_split(const __nv_bfloat16* __restrict__ Ah_, const __nv_bfloat16* __restrict__ Al_,
           const __nv_bfloat16* __restrict__ Bh_, const __nv_bfloat16* __restrict__ Bl_,
           float* __restrict__ Cf,
           __nv_bfloat16* __restrict__ Ch, __nv_bfloat16* __restrict__ Cl,
           int M, int N, int K,
           const float* __restrict__ bias, const float* __restrict__ extra)
{
    __shared__ __nv_bfloat16 Ash[128][40];
    __shared__ __nv_bfloat16 Asl[128][40];
    __shared__ __nv_bfloat16 Bsh[32][136];
    __shared__ __nv_bfloat16 Bsl[32][136];
    __shared__ float stage[8][256];

    const int tid  = threadIdx.x;
    const int wid  = tid >> 5;
    const int lane = tid & 31;
    const int warp_m = wid & 1;    // 2 warps along m: 64 rows each
    const int warp_n = wid >> 1;   // 4 warps along n: 32 cols each
    const int m0 = blockIdx.y * 128;
    const int n0 = blockIdx.x * 128;

    wmma::fragment<wmma::accumulator, 16, 16, 16, float> cf[4][2];
    #pragma unroll
    for (int i = 0; i < 4; i++)
        #pragma unroll
        for (int j = 0; j < 2; j++)
            wmma::fill_fragment(cf[i][j], 0.0f);

    for (int k0 = 0; k0 < K; k0 += 32) {
        // A tiles: 128 rows x 32 cols (hi + lo)
        #pragma unroll
        for (int it = 0; it < 2; it++) {
            int idx = tid + it * 256;
            int row = idx >> 2, g = idx & 3;
            *reinterpret_cast<uint4*>(&Ash[row][g * 8]) =
                *reinterpret_cast<const uint4*>(&Ah_[(size_t)(m0 + row) * K + k0 + g * 8]);
            *reinterpret_cast<uint4*>(&Asl[row][g * 8]) =
                *reinterpret_cast<const uint4*>(&Al_[(size_t)(m0 + row) * K + k0 + g * 8]);
        }
        // B tiles: 32 rows x 128 cols (hi + lo)
        #pragma unroll
        for (int it = 0; it < 2; it++) {
            int idx = tid + it * 256;
            int row = idx >> 4, g = idx & 15;
            *reinterpret_cast<uint4*>(&Bsh[row][g * 8]) =
                *reinterpret_cast<const uint4*>(&Bh_[(size_t)(k0 + row) * N + n0 + g * 8]);
            *reinterpret_cast<uint4*>(&Bsl[row][g * 8]) =
                *reinterpret_cast<const uint4*>(&Bl_[(size_t)(k0 + row) * N + n0 + g * 8]);
        }
        __syncthreads();

        #pragma unroll
        for (int ks = 0; ks < 32; ks += 16) {
            wmma::fragment<wmma::matrix_a, 16, 16, 16, __nv_bfloat16, wmma::row_major> ah[4], al[4];
            wmma::fragment<wmma::matrix_b, 16, 16, 16, __nv_bfloat16, wmma::row_major> bh[2], bl[2];
            #pragma unroll
            for (int i = 0; i < 4; i++) {
                wmma::load_matrix_sync(ah[i], &Ash[warp_m * 64 + i * 16][ks], 40);
                wmma::load_matrix_sync(al[i], &Asl[warp_m * 64 + i * 16][ks], 40);
            }
            #pragma unroll
            for (int j = 0; j < 2; j++) {
                wmma::load_matrix_sync(bh[j], &Bsh[ks][warp_n * 32 + j * 16], 136);
                wmma::load_matrix_sync(bl[j], &Bsl[ks][warp_n * 32 + j * 16], 136);
            }
            #pragma unroll
            for (int i = 0; i < 4; i++)
                #pragma unroll
                for (int j = 0; j < 2; j++) {
                    wmma::mma_sync(cf[i][j], ah[i], bh[j], cf[i][j]);
                    wmma::mma_sync(cf[i][j], al[i], bh[j], cf[i][j]);
                    wmma::mma_sync(cf[i][j], ah[i], bl[j], cf[i][j]);
                }
        }
        __syncthreads();
    }

    // epilogue via per-warp 16x16 staging
    const int r  = lane >> 1;
    const int c0 = (lane & 1) * 8;
    #pragma unroll
    for (int i = 0; i < 4; i++) {
        #pragma unroll
        for (int j = 0; j < 2; j++) {
            wmma::store_matrix_sync(stage[wid], cf[i][j], 16, wmma::mem_row_major);
            __syncwarp();

            const int m = m0 + warp_m * 64 + i * 16 + r;
            const int n = n0 + warp_n * 32 + j * 16 + c0;
            float v[8];
            *reinterpret_cast<float4*>(&v[0]) =
                *reinterpret_cast<const float4*>(&stage[wid][r * 16 + c0]);
            *reinterpret_cast<float4*>(&v[4]) =
                *reinterpret_cast<const float4*>(&stage[wid][r * 16 + c0 + 4]);

            if constexpr (SEPI == 1) {
                #pragma unroll
                for (int t = 0; t < 8; t++) v[t] = fmaxf(v[t] + bias[n + t], 0.0f);
            }
            if constexpr (SEPI == 2) {
                float ex[8];
                *reinterpret_cast<float4*>(&ex[0]) =
                    *reinterpret_cast<const float4*>(&extra[(size_t)m * N + n]);
                *reinterpret_cast<float4*>(&ex[4]) =
                    *reinterpret_cast<const float4*>(&extra[(size_t)m * N + n + 4]);
                #pragma unroll
                for (int t = 0; t < 8; t++) v[t] = tanhf(v[t] + bias[n + t]) + ex[t];
            }

            if constexpr (SEPI == 1 || SEPI == 2) {
                *reinterpret_cast<float4*>(&Cf[(size_t)m * N + n])     = *reinterpret_cast<float4*>(&v[0]);
                *reinterpret_cast<float4*>(&Cf[(size_t)m * N + n + 4]) = *reinterpret_cast<float4*>(&v[4]);
            }

            if constexpr (SEPI == 2) {
                // single-bf16 output (corrb for the Gram kernel)
                __nv_bfloat16 hb[8];
                #pragma unroll
                for (int t = 0; t < 8; t++) hb[t] = __float2bfloat16_rn(v[t]);
                *reinterpret_cast<uint4*>(&Ch[(size_t)m * N + n]) = *reinterpret_cast<uint4*>(hb);
            } else {
                // hi/lo split outputs
                __nv_bfloat16 hb[8], lb[8];
                #pragma unroll
                for (int t = 0; t < 8; t++) {
                    hb[t] = __float2bfloat16_rn(v[t]);
                    lb[t] = __float2bfloat16_rn(v[t] - __bfloat162float(hb[t]));
                }
                *reinterpret_cast<uint4*>(&Ch[(size_t)m * N + n]) = *reinterpret_cast<uint4*>(hb);
                *reinterpret_cast<uint4*>(&Cl[(size_t)m * N + n]) = *reinterpret_cast<uint4*>(lb);
            }
            __syncwarp();
        }
    }
}

// ------------------------- small NN GEMM (scalar FFMA) for the actor head -------------------------
template<int BM, int BN, int BK, int TM, int TN>
__global__ void __launch_bounds__(256)
gemm_nn(const float* __restrict__ A, const float* __restrict__ B,
        float* __restrict__ C, int M, int N, int K,
        const float* __restrict__ bias)
{
    __shared__ float As[BK][BM + 4];
    __shared__ float Bs[BK][BN + 4];

    const int tid = threadIdx.x;
    const int m0 = blockIdx.y * BM;
    const int n0 = blockIdx.x * BN;
    constexpr int TX = BN / TN;
    const int tx = tid % TX;
    const int ty = tid / TX;

    float acc[TM][TN] = {};

    constexpr int LA = BM * BK / (4 * 256);
    constexpr int LB = BK * BN / (4 * 256);

    for (int k0 = 0; k0 < K; k0 += BK) {
        #pragma unroll
        for (int i = 0; i < LA; i++) {
            int f4  = tid + i * 256;
            int row = f4 / (BK / 4);
            int c4  = f4 % (BK / 4);
            float4 v = *reinterpret_cast<const float4*>(&A[(size_t)(m0 + row) * K + k0 + c4 * 4]);
            As[c4 * 4 + 0][row] = v.x;
            As[c4 * 4 + 1][row] = v.y;
            As[c4 * 4 + 2][row] = v.z;
            As[c4 * 4 + 3][row] = v.w;
        }
        #pragma unroll
        for (int i = 0; i < LB; i++) {
            int f4  = tid + i * 256;
            int row = f4 / (BN / 4);
            int c4  = f4 % (BN / 4);
            float4 v = *reinterpret_cast<const float4*>(&B[(size_t)(k0 + row) * N + n0 + c4 * 4]);
            *reinterpret_cast<float4*>(&Bs[row][c4 * 4]) = v;
        }
        __syncthreads();

        #pragma unroll
        for (int k = 0; k < BK; k++) {
            float a[TM], b[TN];
            #pragma unroll
            for (int i = 0; i < TM; i++) a[i] = As[k][ty * TM + i];
            #pragma unroll
            for (int j = 0; j < TN; j++) b[j] = Bs[k][tx * TN + j];
            #pragma unroll
            for (int i = 0; i < TM; i++)
                #pragma unroll
                for (int j = 0; j < TN; j++)
                    acc[i][j] = fmaf(a[i], b[j], acc[i][j]);
        }
        __syncthreads();
    }

    #pragma unroll
    for (int i = 0; i < TM; i++) {
        int m = m0 + ty * TM + i;
        #pragma unroll
        for (int j = 0; j < TN; j++) {
            int n = n0 + tx * TN + j;
            C[(size_t)m * N + n] = acc[i][j] + bias[n];
        }
    }
}

// ------------------------- symmetric Gram via bf16 HMMA + hyperbolic-distance epilogue -------------------------
#define GBK 64
#define GPAD 8
__global__ void __launch_bounds__(256)
gram_dist_wmma(const __nv_bfloat16* __restrict__ Abf, float* __restrict__ S,
               int N, int K,
               const float* __restrict__ norm, const float* __restrict__ rterm,
               const float* __restrict__ cptr)
{
    // --- triangular block decode: blockIdx.x -> (bm, bn), bm <= bn ---
    const int t = blockIdx.x;
    int bm = (int)(((2.0f * NBLK + 1.0f) -
                    sqrtf((float)((2 * NBLK + 1) * (2 * NBLK + 1) - 8 * t))) * 0.5f);
    if (bm < 0) bm = 0;
    if (bm >= NBLK) bm = NBLK - 1;
    #pragma unroll 1
    while (bm + 1 < NBLK && ((bm + 1) * NBLK - (bm * (bm + 1)) / 2) <= t) bm++;
    #pragma unroll 1
    while (bm > 0 && (bm * NBLK - ((bm - 1) * bm) / 2) > t) bm--;
    const int bn = bm + (t - (bm * NBLK - ((bm - 1) * bm) / 2));

    const int m0 = bm * 128;
    const int n0 = bn * 128;

    __shared__ __nv_bfloat16 As[128][GBK + GPAD];
    __shared__ __nv_bfloat16 Bs[128][GBK + GPAD];

    const int tid = threadIdx.x;
    const int wid = tid >> 5;
    const int warp_m = wid & 1;
    const int warp_n = wid >> 1;

    wmma::fragment<wmma::accumulator, 16, 16, 16, float> cf[4][2];
    #pragma unroll
    for (int i = 0; i < 4; i++)
        #pragma unroll
        for (int j = 0; j < 2; j++)
            wmma::fill_fragment(cf[i][j], 0.0f);

    for (int k0 = 0; k0 < K; k0 += GBK) {
        #pragma unroll
        for (int i = 0; i < 4; i++) {
            int idx = tid + i * 256;
            int row = idx >> 3;
            int g   = idx & 7;
            *reinterpret_cast<uint4*>(&As[row][g * 8]) =
                *reinterpret_cast<const uint4*>(&Abf[(size_t)(m0 + row) * K + k0 + g * 8]);
        }
        #pragma unroll
        for (int i = 0; i < 4; i++) {
            int idx = tid + i * 256;
            int row = idx >> 3;
            int g   = idx & 7;
            *reinterpret_cast<uint4*>(&Bs[row][g * 8]) =
                *reinterpret_cast<const uint4*>(&Abf[(size_t)(n0 + row) * K + k0 + g * 8]);
        }
        __syncthreads();

        #pragma unroll
        for (int ks = 0; ks < GBK; ks += 16) {
            wmma::fragment<wmma::matrix_a, 16, 16, 16, __nv_bfloat16, wmma::row_major> af[4];
            wmma::fragment<wmma::matrix_b, 16, 16, 16, __nv_bfloat16, wmma::col_major> bf[2];
            #pragma unroll
            for (int i = 0; i < 4; i++)
                wmma::load_matrix_sync(af[i], &As[warp_m * 64 + i * 16][ks], GBK + GPAD);
            #pragma unroll
            for (int j = 0; j < 2; j++)
                wmma::load_matrix_sync(bf[j], &Bs[warp_n * 32 + j * 16][ks], GBK + GPAD);
            #pragma unroll
            for (int i = 0; i < 4; i++)
                #pragma unroll
                for (int j = 0; j < 2; j++)
                    wmma::mma_sync(cf[i][j], af[i], bf[j], cf[i][j]);
        }
        __syncthreads();
    }

    // stage raw Gram values into the S tile
    #pragma unroll
    for (int i = 0; i < 4; i++) {
        #pragma unroll
        for (int j = 0; j < 2; j++) {
            int m = m0 + warp_m * 64 + i * 16;
            int n = n0 + warp_n * 32 + j * 16;
            wmma::store_matrix_sync(&S[(size_t)m * N + n], cf[i][j], N, wmma::mem_row_major);
        }
    }
    __syncthreads();

    // epilogue: read raw g, write dist to S[m][n] and mirror S[n][m]
    const float cc     = fmaxf(cptr[0], EPSF);
    const float isc    = rsqrtf(cc);
    const float two_cc = 2.0f * cc;
    const bool  diag   = (bm == bn);

    for (int idx = tid; idx < 128 * 128; idx += 256) {
        int i = idx >> 7, j = idx & 127;
        if (diag && j < i) continue;
        int m = m0 + i, n = n0 + j;
        float g  = S[(size_t)m * N + n];
        float d2 = (m == n) ? 0.0f : fmaxf(norm[m] + norm[n] - 2.0f * g, 0.0f);
        float arg = fmaf(two_cc * d2, rterm[m] * rterm[n], 1.0f);
        arg = fmaxf(arg, 1.0f + EPSF) + EPSF;
        float v = -__logf(arg + __fsqrt_rn(fmaf(arg, arg, -1.0f))) * isc;
        S[(size_t)m * N + n] = v;
        if (m != n) S[(size_t)n * N + m] = v;
    }
}

// ------------------------- row squared norms + 1/term -------------------------
__global__ void row_norms(const float* __restrict__ X, float* __restrict__ norm,
                          float* __restrict__ rterm,
                          const float* __restrict__ cptr, int B, int D)
{
    int warp = (blockIdx.x * blockDim.x + threadIdx.x) >> 5;
    int lane = threadIdx.x & 31;
    if (warp >= B) return;
    const float* x = X + (size_t)warp * D;
    float s = 0.0f;
    for (int k = lane; k < D; k += 32) { float v = x[k]; s = fmaf(v, v, s); }
    #pragma unroll
    for (int o = 16; o; o >>= 1) s += __shfl_xor_sync(0xFFFFFFFFu, s, o);
    if (lane == 0) {
        norm[warp] = s;
        float cc = fmaxf(cptr[0], EPSF);
        float t  = fmaxf(1.0f - cc * s, EPSF);
        rterm[warp] = 1.0f / t;
    }
}

// ------------------------- row softmax + sparsity compaction -------------------------
__global__ void __launch_bounds__(256)
softmax_compact(const float* __restrict__ S, int* __restrict__ spi,
                float* __restrict__ spv, int* __restrict__ cnt, int N)
{
    __shared__ float buf[BATCH];
    __shared__ float red[32];
    __shared__ int   wbase[8];
    const int tid = threadIdx.x;
    const int row = blockIdx.x;
    const float* Sr = S + (size_t)row * N;

    float mx = -3.4e38f;
    for (int i = tid; i < N; i += 256) { float v = Sr[i]; buf[i] = v; mx = fmaxf(mx, v); }
    #pragma unroll
    for (int o = 16; o; o >>= 1) mx = fmaxf(mx, __shfl_xor_sync(0xFFFFFFFFu, mx, o));
    if ((tid & 31) == 0) red[tid >> 5] = mx;
    __syncthreads();
    if (tid < 32) {
        float v = (tid < 8) ? red[tid] : -3.4e38f;
        #pragma unroll
        for (int o = 4; o; o >>= 1) v = fmaxf(v, __shfl_xor_sync(0xFFFFFFFFu, v, o));
        if (tid == 0) red[0] = v;
    }
    __syncthreads();
    mx = red[0];

    float sum = 0.0f;
    for (int i = tid; i < N; i += 256) { float e = __expf(buf[i] - mx); buf[i] = e; sum += e; }
    __syncthreads();
    #pragma unroll
    for (int o = 16; o; o >>= 1) sum += __shfl_xor_sync(0xFFFFFFFFu, sum, o);
    if ((tid & 31) == 0) red[tid >> 5] = sum;
    __syncthreads();
    if (tid < 32) {
        float v = (tid < 8) ? red[tid] : 0.0f;
        #pragma unroll
        for (int o = 4; o; o >>= 1) v += __shfl_xor_sync(0xFFFFFFFFu, v, o);
        if (tid == 0) red[0] = v;
    }
    __syncthreads();
    const float inv = 1.0f / red[0];

    int c = 0;
    for (int i = tid; i < N; i += 256)
        if (buf[i] * inv >= P_THRESH) c++;

    int lane = tid & 31, w = tid >> 5;
    int incl = c;
    #pragma unroll
    for (int o = 1; o < 32; o <<= 1) {
        int t = __shfl_up_sync(0xFFFFFFFFu, incl, o);
        if (lane >= o) incl += t;
    }
    if (lane == 31) wbase[w] = incl;
    __syncthreads();
    if (tid == 0) {
        int s = 0;
        #pragma unroll
        for (int k = 0; k < 8; k++) { int t = wbase[k]; wbase[k] = s; s += t; }
        cnt[row] = s;
    }
    __syncthreads();
    int pos = wbase[w] + incl - c;

    for (int i = tid; i < N; i += 256) {
        float p = buf[i] * inv;
        if (p >= P_THRESH) {
            spi[(size_t)row * N + pos] = i;
            spv[(size_t)row * N + pos] = p;
            pos++;
        }
    }
}

// ------------------------- sparse attn -------------------------
__global__ void __launch_bounds__(256)
attn_sparse(const int* __restrict__ spi, const float* __restrict__ spv,
            const int* __restrict__ cnt, const float* __restrict__ corr,
            float* __restrict__ attn)
{
    const int row = blockIdx.x;
    const int tid = threadIdx.x;
    const int n = cnt[row];
    const float4* corr4 = reinterpret_cast<const float4*>(corr);
    float4 acc = make_float4(0.f, 0.f, 0.f, 0.f);
    for (int t = 0; t < n; t++) {
        int   idx = spi[(size_t)row * BATCH + t];
        float v   = spv[(size_t)row * BATCH + t];
        float4 x  = corr4[(size_t)idx * (HIDDIM / 4) + tid];
        acc.x = fmaf(v, x.x, acc.x);
        acc.y = fmaf(v, x.y, acc.y);
        acc.z = fmaf(v, x.z, acc.z);
        acc.w = fmaf(v, x.w, acc.w);
    }
    reinterpret_cast<float4*>(attn)[(size_t)row * (HIDDIM / 4) + tid] = acc;
}

// ------------------------- heads epilogue -------------------------
__global__ void heads_epilogue(const float* __restrict__ logits,
                               const float* __restrict__ attn,
                               const float* __restrict__ W_risk,
                               const float* __restrict__ b_risk,
                               float* __restrict__ probs,
                               float* __restrict__ risk,
                               int B, int D)
{
    int warp = (blockIdx.x * blockDim.x + threadIdx.x) >> 5;
    int lane = threadIdx.x & 31;
    if (warp >= B) return;

    const float* ar = attn + (size_t)warp * D;
    float s = 0.0f;
    for (int k = lane; k < D; k += 32) s = fmaf(ar[k], W_risk[k], s);
    #pragma unroll
    for (int o = 16; o; o >>= 1) s += __shfl_xor_sync(0xFFFFFFFFu, s, o);
    if (lane == 0) risk[warp] = 1.0f / (1.0f + expf(-(s + b_risk[0])));

    const float* lr = logits + (size_t)warp * ACTDIM;
    float v0 = lr[lane], v1 = lr[lane + 32];
    float mx = fmaxf(v0, v1);
    #pragma unroll
    for (int o = 16; o; o >>= 1) mx = fmaxf(mx, __shfl_xor_sync(0xFFFFFFFFu, mx, o));
    float e0 = expf(v0 - mx), e1 = expf(v1 - mx);
    float ss = e0 + e1;
    #pragma unroll
    for (int o = 16; o; o >>= 1) ss += __shfl_xor_sync(0xFFFFFFFFu, ss, o);
    float inv = 1.0f / ss;
    probs[(size_t)warp * ACTDIM + lane]      = e0 * inv;
    probs[(size_t)warp * ACTDIM + lane + 32] = e1 * inv;
}

// ------------------------- launch -------------------------
extern "C" void kernel_launch(void* const* d_in, const int* in_sizes, int n_in,
                              void* d_out, int out_size)
{
    const float* state   = (const float*)d_in[0];
    const float* W_enc   = (const float*)d_in[1];
    const float* b_enc   = (const float*)d_in[2];
    const float* cov     = (const float*)d_in[3];
    const float* W_phase = (const float*)d_in[4];
    const float* b_phase = (const float*)d_in[5];
    const float* cptr    = (const float*)d_in[6];
    const float* W_actor = (const float*)d_in[7];
    const float* b_actor = (const float*)d_in[8];
    const float* W_risk  = (const float*)d_in[9];
    const float* b_risk  = (const float*)d_in[10];

    float* out    = (float*)d_out;
    float* logits = out;
    float* probs  = out + (size_t)BATCH * ACTDIM;
    float* risk   = out + (size_t)2 * BATCH * ACTDIM;

    float *enc, *corr, *attn, *nrm, *rterm, *S, *spv;
    __nv_bfloat16 *corrb, *sth, *stl, *weh, *wel, *cvh, *cvl, *wph, *wpl,
                  *ench, *encl, *t1h, *t1l;
    int *spi, *cnt;
    cudaGetSymbolAddress((void**)&enc,   g_enc);
    cudaGetSymbolAddress((void**)&corr,  g_corr);
    cudaGetSymbolAddress((void**)&corrb, g_corrb);
    cudaGetSymbolAddress((void**)&attn,  g_attn);
    cudaGetSymbolAddress((void**)&nrm,   g_norm);
    cudaGetSymbolAddress((void**)&rterm, g_rterm);
    cudaGetSymbolAddress((void**)&S,     g_S);
    cudaGetSymbolAddress((void**)&spi,   g_spi);
    cudaGetSymbolAddress((void**)&spv,   g_spv);
    cudaGetSymbolAddress((void**)&cnt,   g_cnt);
    cudaGetSymbolAddress((void**)&sth,   g_state_h);
    cudaGetSymbolAddress((void**)&stl,   g_state_l);
    cudaGetSymbolAddress((void**)&weh,   g_Wenc_h);
    cudaGetSymbolAddress((void**)&wel,   g_Wenc_l);
    cudaGetSymbolAddress((void**)&cvh,   g_cov_h);
    cudaGetSymbolAddress((void**)&cvl,   g_cov_l);
    cudaGetSymbolAddress((void**)&wph,   g_Wph_h);
    cudaGetSymbolAddress((void**)&wpl,   g_Wph_l);
    cudaGetSymbolAddress((void**)&ench,  g_enc_h);
    cudaGetSymbolAddress((void**)&encl,  g_enc_l);
    cudaGetSymbolAddress((void**)&t1h,   g_t1_h);
    cudaGetSymbolAddress((void**)&t1l,   g_t1_l);

    // 0) split inputs to (hi, lo) bf16
    split_bf16<<<(BATCH * INDIM)   / 1024, 256>>>(state,   sth, stl);
    split_bf16<<<(INDIM * HIDDIM)  / 1024, 256>>>(W_enc,   weh, wel);
    split_bf16<<<(HIDDIM * HIDDIM) / 1024, 256>>>(cov,     cvh, cvl);
    split_bf16<<<(HIDDIM * HIDDIM) / 1024, 256>>>(W_phase, wph, wpl);

    // 1) enc = relu(state @ W_enc + b_enc)  -> enc fp32 + (hi, lo)
    gemm_split<1><<<dim3(HIDDIM / 128, BATCH / 128), 256>>>(
        sth, stl, weh, wel, enc, ench, encl, BATCH, HIDDIM, INDIM, b_enc, nullptr);

    // 2) t1 = enc @ cov  -> (hi, lo) only
    gemm_split<0><<<dim3(HIDDIM / 128, BATCH / 128), 256>>>(
        ench, encl, cvh, cvl, nullptr, t1h, t1l, BATCH, HIDDIM, HIDDIM, nullptr, nullptr);

    // 3) corr = tanh(t1 @ W_phase + b_phase) + enc  -> corr fp32 + corrb bf16
    gemm_split<2><<<dim3(HIDDIM / 128, BATCH / 128), 256>>>(
        t1h, t1l, wph, wpl, corr, corrb, nullptr, BATCH, HIDDIM, HIDDIM, b_phase, enc);

    // 4) per-row squared norms + 1/term
    row_norms<<<BATCH / 8, 256>>>(corr, nrm, rterm, cptr, BATCH, HIDDIM);

    // 5) S = -dist(corr, corr): bf16 HMMA Gram, upper-tri blocks + mirror store
    gram_dist_wmma<<<NBLK * (NBLK + 1) / 2, 256>>>(
        corrb, S, BATCH, HIDDIM, nrm, rterm, cptr);

    // 6) softmax rows + sparsity compaction
    softmax_compact<<<BATCH, 256>>>(S, spi, spv, cnt, BATCH);

    // 7) attn = P @ corr (sparse)
    attn_sparse<<<BATCH, 256>>>(spi, spv, cnt, corr, attn);

    // 8) logits = attn @ W_actor + b_actor
    gemm_nn<128, 64, 16, 8, 4><<<dim3(ACTDIM / 64, BATCH / 128), 256>>>(
        attn, W_actor, logits, BATCH, ACTDIM, HIDDIM, b_actor);

    // 9) probs + risk
    heads_epilogue<<<BATCH / 8, 256>>>(logits, attn, W_risk, b_risk, probs, risk, BATCH, HIDDIM);
}

// round 16
// speedup vs baseline: 6.3895x; 1.0312x over previous
#include <cuda_runtime.h>
#include <cuda_bf16.h>
#include <mma.h>
#include <math.h>

using namespace nvcuda;

#define EPSF 1e-6f

#define BATCH 8192
#define INDIM 512
#define HIDDIM 1024
#define ACTDIM 64

// Sparsity threshold for softmax weights. Dropped probability mass per row is
// bounded by 8192 * 1e-9 = 8.2e-6 -> |attn error| ~ 2e-5 absolute, two orders
// below the 1e-3 correctness gate. Input-independent bound.
#define P_THRESH 1e-9f

// Candidate filter margin in dist units: entries with dist - dist_min > 30
// have softmax weight <= e^-30 ~ 9e-14 each; 8192 of them contribute <= 7.7e-10
// of the softmax sum (which is >= 1). Both exclusion effects are ~1e5x below
// P_THRESH / fp32 resolution for ANY input.
#define CAND_MARGIN 30.0f

#define NBLK (BATCH / 128)

// ------------------------- scratch (no cudaMalloc allowed) -------------------------
__device__ float          g_enc  [(size_t)BATCH * HIDDIM];
__device__ float          g_corr [(size_t)BATCH * HIDDIM];
__device__ __nv_bfloat16  g_corrb[(size_t)BATCH * HIDDIM];
__device__ float          g_attn [(size_t)BATCH * HIDDIM];
__device__ float          g_norm [BATCH];
__device__ float          g_rterm[BATCH];
__device__ float          g_S    [(size_t)BATCH * BATCH];   // holds "arg" values
__device__ int            g_spi  [(size_t)BATCH * BATCH];
__device__ float          g_spv  [(size_t)BATCH * BATCH];
__device__ int            g_cnt  [BATCH];

// split-bf16 operands (hi/lo pairs)
__device__ __nv_bfloat16  g_state_h[(size_t)BATCH * INDIM];
__device__ __nv_bfloat16  g_state_l[(size_t)BATCH * INDIM];
__device__ __nv_bfloat16  g_Wenc_h [(size_t)INDIM * HIDDIM];
__device__ __nv_bfloat16  g_Wenc_l [(size_t)INDIM * HIDDIM];
__device__ __nv_bfloat16  g_cov_h  [(size_t)HIDDIM * HIDDIM];
__device__ __nv_bfloat16  g_cov_l  [(size_t)HIDDIM * HIDDIM];
__device__ __nv_bfloat16  g_Wph_h  [(size_t)HIDDIM * HIDDIM];
__device__ __nv_bfloat16  g_Wph_l  [(size_t)HIDDIM * HIDDIM];
__device__ __nv_bfloat16  g_enc_h  [(size_t)BATCH * HIDDIM];
__device__ __nv_bfloat16  g_enc_l  [(size_t)BATCH * HIDDIM];
__device__ __nv_bfloat16  g_t1_h   [(size_t)BATCH * HIDDIM];
__device__ __nv_bfloat16  g_t1_l   [(size_t)BATCH * HIDDIM];

// ------------------------- fp32 -> (hi, lo) bf16 split -------------------------
__global__ void split_bf16(const float* __restrict__ x,
                           __nv_bfloat16* __restrict__ h,
                           __nv_bfloat16* __restrict__ l)
{
    size_t i = ((size_t)blockIdx.x * blockDim.x + threadIdx.x) * 4;
    float4 v = *reinterpret_cast<const float4*>(&x[i]);
    __nv_bfloat16 hv[4], lv[4];
    float vv[4] = {v.x, v.y, v.z, v.w};
    #pragma unroll
    for (int t = 0; t < 4; t++) {
        hv[t] = __float2bfloat16_rn(vv[t]);
        lv[t] = __float2bfloat16_rn(vv[t] - __bfloat162float(hv[t]));
    }
    *reinterpret_cast<uint2*>(&h[i]) = *reinterpret_cast<uint2*>(hv);
    *reinterpret_cast<uint2*>(&l[i]) = *reinterpret_cast<uint2*>(lv);
}

// ------------------------- split-bf16 wmma GEMM with fused epilogues -------------------------
// C = epi(A @ B) where A = Ah + Al, B = Bh + Bl (bf16 splits of fp32 matrices).
// SEPI 1: v = relu(acc + bias[n]); write Cf (fp32) + Ch/Cl (bf16 split of v)
// SEPI 0: v = acc;                 write Ch/Cl only
// SEPI 2: v = tanh(acc + bias[n]) + extra[m,n]; write Cf + Ch (single bf16)
template<int SEPI>
__global__ void __launch_bounds__(256)
gemm_split(const __nv_bfloat16* __restrict__ Ah_, const __nv_bfloat16* __restrict__ Al_,
           const __nv_bfloat16* __restrict__ Bh_, const __nv_bfloat16* __restrict__ Bl_,
           float* __restrict__ Cf,
           __nv_bfloat16* __restrict__ Ch, __nv_bfloat16* __restrict__ Cl,
           int M, int N, int K,
           const float* __restrict__ bias, const float* __restrict__ extra)
{
    __shared__ __nv_bfloat16 Ash[128][40];
    __shared__ __nv_bfloat16 Asl[128][40];
    __shared__ __nv_bfloat16 Bsh[32][136];
    __shared__ __nv_bfloat16 Bsl[32][136];
    __shared__ float stage[8][256];

    const int tid  = threadIdx.x;
    const int wid  = tid >> 5;
    const int lane = tid & 31;
    const int warp_m = wid & 1;
    const int warp_n = wid >> 1;
    const int m0 = blockIdx.y * 128;
    const int n0 = blockIdx.x * 128;

    wmma::fragment<wmma::accumulator, 16, 16, 16, float> cf[4][2];
    #pragma unroll
    for (int i = 0; i < 4; i++)
        #pragma unroll
        for (int j = 0; j < 2; j++)
            wmma::fill_fragment(cf[i][j], 0.0f);

    for (int k0 = 0; k0 < K; k0 += 32) {
        #pragma unroll
        for (int it = 0; it < 2; it++) {
            int idx = tid + it * 256;
            int row = idx >> 2, g = idx & 3;
            *reinterpret_cast<uint4*>(&Ash[row][g * 8]) =
                *reinterpret_cast<const uint4*>(&Ah_[(size_t)(m0 + row) * K + k0 + g * 8]);
            *reinterpret_cast<uint4*>(&Asl[row][g * 8]) =
                *reinterpret_cast<const uint4*>(&Al_[(size_t)(m0 + row) * K + k0 + g * 8]);
        }
        #pragma unroll
        for (int it = 0; it < 2; it++) {
            int idx = tid + it * 256;
            int row = idx >> 4, g = idx & 15;
            *reinterpret_cast<uint4*>(&Bsh[row][g * 8]) =
                *reinterpret_cast<const uint4*>(&Bh_[(size_t)(k0 + row) * N + n0 + g * 8]);
            *reinterpret_cast<uint4*>(&Bsl[row][g * 8]) =
                *reinterpret_cast<const uint4*>(&Bl_[(size_t)(k0 + row) * N + n0 + g * 8]);
        }
        __syncthreads();

        #pragma unroll
        for (int ks = 0; ks < 32; ks += 16) {
            wmma::fragment<wmma::matrix_a, 16, 16, 16, __nv_bfloat16, wmma::row_major> ah[4], al[4];
            wmma::fragment<wmma::matrix_b, 16, 16, 16, __nv_bfloat16, wmma::row_major> bh[2], bl[2];
            #pragma unroll
            for (int i = 0; i < 4; i++) {
                wmma::load_matrix_sync(ah[i], &Ash[warp_m * 64 + i * 16][ks], 40);
                wmma::load_matrix_sync(al[i], &Asl[warp_m * 64 + i * 16][ks], 40);
            }
            #pragma unroll
            for (int j = 0; j < 2; j++) {
                wmma::load_matrix_sync(bh[j], &Bsh[ks][warp_n * 32 + j * 16], 136);
                wmma::load_matrix_sync(bl[j], &Bsl[ks][warp_n * 32 + j * 16], 136);
            }
            #pragma unroll
            for (int i = 0; i < 4; i++)
                #pragma unroll
                for (int j = 0; j < 2; j++) {
                    wmma::mma_sync(cf[i][j], ah[i], bh[j], cf[i][j]);
                    wmma::mma_sync(cf[i][j], al[i], bh[j], cf[i][j]);
                    wmma::mma_sync(cf[i][j], ah[i], bl[j], cf[i][j]);
                }
        }
        __syncthreads();
    }

    const int r  = lane >> 1;
    const int c0 = (lane & 1) * 8;
    #pragma unroll
    for (int i = 0; i < 4; i++) {
        #pragma unroll
        for (int j = 0; j < 2; j++) {
            wmma::store_matrix_sync(stage[wid], cf[i][j], 16, wmma::mem_row_major);
            __syncwarp();

            const int m = m0 + warp_m * 64 + i * 16 + r;
            const int n = n0 + warp_n * 32 + j * 16 + c0;
            float v[8];
            *reinterpret_cast<float4*>(&v[0]) =
                *reinterpret_cast<const float4*>(&stage[wid][r * 16 + c0]);
            *reinterpret_cast<float4*>(&v[4]) =
                *reinterpret_cast<const float4*>(&stage[wid][r * 16 + c0 + 4]);

            if constexpr (SEPI == 1) {
                #pragma unroll
                for (int t = 0; t < 8; t++) v[t] = fmaxf(v[t] + bias[n + t], 0.0f);
            }
            if constexpr (SEPI == 2) {
                float ex[8];
                *reinterpret_cast<float4*>(&ex[0]) =
                    *reinterpret_cast<const float4*>(&extra[(size_t)m * N + n]);
                *reinterpret_cast<float4*>(&ex[4]) =
                    *reinterpret_cast<const float4*>(&extra[(size_t)m * N + n + 4]);
                #pragma unroll
                for (int t = 0; t < 8; t++) v[t] = tanhf(v[t] + bias[n + t]) + ex[t];
            }

            if constexpr (SEPI == 1 || SEPI == 2) {
                *reinterpret_cast<float4*>(&Cf[(size_t)m * N + n])     = *reinterpret_cast<float4*>(&v[0]);
                *reinterpret_cast<float4*>(&Cf[(size_t)m * N + n + 4]) = *reinterpret_cast<float4*>(&v[4]);
            }

            if constexpr (SEPI == 2) {
                __nv_bfloat16 hb[8];
                #pragma unroll
                for (int t = 0; t < 8; t++) hb[t] = __float2bfloat16_rn(v[t]);
                *reinterpret_cast<uint4*>(&Ch[(size_t)m * N + n]) = *reinterpret_cast<uint4*>(hb);
            } else {
                __nv_bfloat16 hb[8], lb[8];
                #pragma unroll
                for (int t = 0; t < 8; t++) {
                    hb[t] = __float2bfloat16_rn(v[t]);
                    lb[t] = __float2bfloat16_rn(v[t] - __bfloat162float(hb[t]));
                }
                *reinterpret_cast<uint4*>(&Ch[(size_t)m * N + n]) = *reinterpret_cast<uint4*>(hb);
                *reinterpret_cast<uint4*>(&Cl[(size_t)m * N + n]) = *reinterpret_cast<uint4*>(lb);
            }
            __syncwarp();
        }
    }
}

// ------------------------- small NN GEMM (scalar FFMA) for the actor head -------------------------
template<int BM, int BN, int BK, int TM, int TN>
__global__ void __launch_bounds__(256)
gemm_nn(const float* __restrict__ A, const float* __restrict__ B,
        float* __restrict__ C, int M, int N, int K,
        const float* __restrict__ bias)
{
    __shared__ float As[BK][BM + 4];
    __shared__ float Bs[BK][BN + 4];

    const int tid = threadIdx.x;
    const int m0 = blockIdx.y * BM;
    const int n0 = blockIdx.x * BN;
    constexpr int TX = BN / TN;
    const int tx = tid % TX;
    const int ty = tid / TX;

    float acc[TM][TN] = {};

    constexpr int LA = BM * BK / (4 * 256);
    constexpr int LB = BK * BN / (4 * 256);

    for (int k0 = 0; k0 < K; k0 += BK) {
        #pragma unroll
        for (int i = 0; i < LA; i++) {
            int f4  = tid + i * 256;
            int row = f4 / (BK / 4);
            int c4  = f4 % (BK / 4);
            float4 v = *reinterpret_cast<const float4*>(&A[(size_t)(m0 + row) * K + k0 + c4 * 4]);
            As[c4 * 4 + 0][row] = v.x;
            As[c4 * 4 + 1][row] = v.y;
            As[c4 * 4 + 2][row] = v.z;
            As[c4 * 4 + 3][row] = v.w;
        }
        #pragma unroll
        for (int i = 0; i < LB; i++) {
            int f4  = tid + i * 256;
            int row = f4 / (BN / 4);
            int c4  = f4 % (BN / 4);
            float4 v = *reinterpret_cast<const float4*>(&B[(size_t)(k0 + row) * N + n0 + c4 * 4]);
            *reinterpret_cast<float4*>(&Bs[row][c4 * 4]) = v;
        }
        __syncthreads();

        #pragma unroll
        for (int k = 0; k < BK; k++) {
            float a[TM], b[TN];
            #pragma unroll
            for (int i = 0; i < TM; i++) a[i] = As[k][ty * TM + i];
            #pragma unroll
            for (int j = 0; j < TN; j++) b[j] = Bs[k][tx * TN + j];
            #pragma unroll
            for (int i = 0; i < TM; i++)
                #pragma unroll
                for (int j = 0; j < TN; j++)
                    acc[i][j] = fmaf(a[i], b[j], acc[i][j]);
        }
        __syncthreads();
    }

    #pragma unroll
    for (int i = 0; i < TM; i++) {
        int m = m0 + ty * TM + i;
        #pragma unroll
        for (int j = 0; j < TN; j++) {
            int n = n0 + tx * TN + j;
            C[(size_t)m * N + n] = acc[i][j] + bias[n];
        }
    }
}

// ------------------------- symmetric Gram via bf16 HMMA; stores "arg" (no MUFU) -------------------------
// Upper-triangular 128x128 blocks only; off-diagonal blocks also store the
// mirrored tile. Epilogue stores arg = clamp(1 + 2c*d2/(term_m*term_n)) -- the
// acosh argument. acosh is monotonic, so softmax can rank rows by arg directly
// and spend transcendentals only on surviving candidates.
// d2(m,m) = 0 exactly (mathematical identity) -> diagonal is the exact row min.
#define GBK 64
#define GPAD 8
__global__ void __launch_bounds__(256)
gram_arg_wmma(const __nv_bfloat16* __restrict__ Abf, float* __restrict__ S,
              int N, int K,
              const float* __restrict__ norm, const float* __restrict__ rterm,
              const float* __restrict__ cptr)
{
    // --- triangular block decode: blockIdx.x -> (bm, bn), bm <= bn ---
    const int t = blockIdx.x;
    int bm = (int)(((2.0f * NBLK + 1.0f) -
                    sqrtf((float)((2 * NBLK + 1) * (2 * NBLK + 1) - 8 * t))) * 0.5f);
    if (bm < 0) bm = 0;
    if (bm >= NBLK) bm = NBLK - 1;
    #pragma unroll 1
    while (bm + 1 < NBLK && ((bm + 1) * NBLK - (bm * (bm + 1)) / 2) <= t) bm++;
    #pragma unroll 1
    while (bm > 0 && (bm * NBLK - ((bm - 1) * bm) / 2) > t) bm--;
    const int bn = bm + (t - (bm * NBLK - ((bm - 1) * bm) / 2));

    const int m0 = bm * 128;
    const int n0 = bn * 128;

    __shared__ __nv_bfloat16 As[128][GBK + GPAD];
    __shared__ __nv_bfloat16 Bs[128][GBK + GPAD];

    const int tid = threadIdx.x;
    const int wid = tid >> 5;
    const int warp_m = wid & 1;
    const int warp_n = wid >> 1;

    wmma::fragment<wmma::accumulator, 16, 16, 16, float> cf[4][2];
    #pragma unroll
    for (int i = 0; i < 4; i++)
        #pragma unroll
        for (int j = 0; j < 2; j++)
            wmma::fill_fragment(cf[i][j], 0.0f);

    for (int k0 = 0; k0 < K; k0 += GBK) {
        #pragma unroll
        for (int i = 0; i < 4; i++) {
            int idx = tid + i * 256;
            int row = idx >> 3;
            int g   = idx & 7;
            *reinterpret_cast<uint4*>(&As[row][g * 8]) =
                *reinterpret_cast<const uint4*>(&Abf[(size_t)(m0 + row) * K + k0 + g * 8]);
        }
        #pragma unroll
        for (int i = 0; i < 4; i++) {
            int idx = tid + i * 256;
            int row = idx >> 3;
            int g   = idx & 7;
            *reinterpret_cast<uint4*>(&Bs[row][g * 8]) =
                *reinterpret_cast<const uint4*>(&Abf[(size_t)(n0 + row) * K + k0 + g * 8]);
        }
        __syncthreads();

        #pragma unroll
        for (int ks = 0; ks < GBK; ks += 16) {
            wmma::fragment<wmma::matrix_a, 16, 16, 16, __nv_bfloat16, wmma::row_major> af[4];
            wmma::fragment<wmma::matrix_b, 16, 16, 16, __nv_bfloat16, wmma::col_major> bf[2];
            #pragma unroll
            for (int i = 0; i < 4; i++)
                wmma::load_matrix_sync(af[i], &As[warp_m * 64 + i * 16][ks], GBK + GPAD);
            #pragma unroll
            for (int j = 0; j < 2; j++)
                wmma::load_matrix_sync(bf[j], &Bs[warp_n * 32 + j * 16][ks], GBK + GPAD);
            #pragma unroll
            for (int i = 0; i < 4; i++)
                #pragma unroll
                for (int j = 0; j < 2; j++)
                    wmma::mma_sync(cf[i][j], af[i], bf[j], cf[i][j]);
        }
        __syncthreads();
    }

    // stage raw Gram values into the S tile
    #pragma unroll
    for (int i = 0; i < 4; i++) {
        #pragma unroll
        for (int j = 0; j < 2; j++) {
            int m = m0 + warp_m * 64 + i * 16;
            int n = n0 + warp_n * 32 + j * 16;
            wmma::store_matrix_sync(&S[(size_t)m * N + n], cf[i][j], N, wmma::mem_row_major);
        }
    }
    __syncthreads();   // block-scope visibility of global writes

    // epilogue: read raw g, write arg to S[m][n] and mirror S[n][m] (no MUFU)
    const float cc     = fmaxf(cptr[0], EPSF);
    const float two_cc = 2.0f * cc;
    const bool  diag   = (bm == bn);

    for (int idx = tid; idx < 128 * 128; idx += 256) {
        int i = idx >> 7, j = idx & 127;
        if (diag && j < i) continue;
        int m = m0 + i, n = n0 + j;
        float g  = S[(size_t)m * N + n];
        float d2 = (m == n) ? 0.0f : fmaxf(norm[m] + norm[n] - 2.0f * g, 0.0f);
        float arg = fmaf(two_cc * d2, rterm[m] * rterm[n], 1.0f);
        arg = fmaxf(arg, 1.0f + EPSF) + EPSF;
        S[(size_t)m * N + n] = arg;
        if (m != n) S[(size_t)n * N + m] = arg;
    }
}

// ------------------------- row squared norms + 1/term -------------------------
__global__ void row_norms(const float* __restrict__ X, float* __restrict__ norm,
                          float* __restrict__ rterm,
                          const float* __restrict__ cptr, int B, int D)
{
    int warp = (blockIdx.x * blockDim.x + threadIdx.x) >> 5;
    int lane = threadIdx.x & 31;
    if (warp >= B) return;
    const float* x = X + (size_t)warp * D;
    float s = 0.0f;
    for (int k = lane; k < D; k += 32) { float v = x[k]; s = fmaf(v, v, s); }
    #pragma unroll
    for (int o = 16; o; o >>= 1) s += __shfl_xor_sync(0xFFFFFFFFu, s, o);
    if (lane == 0) {
        norm[warp] = s;
        float cc = fmaxf(cptr[0], EPSF);
        float t  = fmaxf(1.0f - cc * s, EPSF);
        rterm[warp] = 1.0f / t;
    }
}

// ------------------------- row softmax + sparsity compaction over arg values -------------------------
// S holds arg (acosh argument). dist = acosh(arg)/sqrt(c) is monotonic in arg,
// so: row max of s=-dist <=> row min of arg. Entries with
// acosh(arg) > acosh(arg_min) + CAND_MARGIN*sqrt(c) have softmax weight
// <= e^-CAND_MARGIN and are provably irrelevant (see CAND_MARGIN comment).
// Transcendentals run only on candidates (typically 1/row; degrades gracefully
// to dense if the data demands it).
__global__ void __launch_bounds__(256)
softmax_compact(const float* __restrict__ S, int* __restrict__ spi,
                float* __restrict__ spv, int* __restrict__ cnt, int N,
                const float* __restrict__ cptr)
{
    __shared__ float buf[BATCH];
    __shared__ float red[32];
    __shared__ int   wbase[8];
    __shared__ float sh_smax, sh_th;
    const int tid = threadIdx.x;
    const int row = blockIdx.x;
    const float* Sr = S + (size_t)row * N;

    const float cc  = fmaxf(cptr[0], EPSF);
    const float isc = rsqrtf(cc);

    // --- pass 1: load arg, row min ---
    float mn = 3.4e38f;
    for (int i = tid; i < N; i += 256) { float v = Sr[i]; buf[i] = v; mn = fminf(mn, v); }
    #pragma unroll
    for (int o = 16; o; o >>= 1) mn = fminf(mn, __shfl_xor_sync(0xFFFFFFFFu, mn, o));
    if ((tid & 31) == 0) red[tid >> 5] = mn;
    __syncthreads();
    if (tid < 32) {
        float v = (tid < 8) ? red[tid] : 3.4e38f;
        #pragma unroll
        for (int o = 4; o; o >>= 1) v = fminf(v, __shfl_xor_sync(0xFFFFFFFFu, v, o));
        if (tid == 0) {
            float am = acoshf(v);
            sh_smax = -am * isc;                       // exact row max of s
            sh_th   = coshf(am + CAND_MARGIN * sqrtf(cc));  // arg-space candidate bound
        }
    }
    __syncthreads();
    const float smax = sh_smax;
    const float th   = sh_th;

    // --- pass 2: candidates only: e = exp(s - smax); store -e in buf; sum ---
    // (non-candidates keep arg >= 1 > 0 in buf; candidates hold -e < 0)
    float sum = 0.0f;
    for (int i = tid; i < N; i += 256) {
        float a = buf[i];
        if (a <= th) {
            float s = -acoshf(a) * isc;
            float e = expf(s - smax);
            buf[i] = -e;
            sum += e;
        }
    }
    __syncthreads();   // red[] reads from pass 1 complete
    #pragma unroll
    for (int o = 16; o; o >>= 1) sum += __shfl_xor_sync(0xFFFFFFFFu, sum, o);
    if ((tid & 31) == 0) red[tid >> 5] = sum;
    __syncthreads();
    if (tid < 32) {
        float v = (tid < 8) ? red[tid] : 0.0f;
        #pragma unroll
        for (int o = 4; o; o >>= 1) v += __shfl_xor_sync(0xFFFFFFFFu, v, o);
        if (tid == 0) red[0] = v;
    }
    __syncthreads();
    const float inv = 1.0f / red[0];

    // --- pass 3: count survivors (p >= P_THRESH) ---
    int c = 0;
    for (int i = tid; i < N; i += 256) {
        float b = buf[i];
        if (b < 0.0f && (-b) * inv >= P_THRESH) c++;
    }

    // --- deterministic exclusive scan over 256 threads ---
    int lane = tid & 31, w = tid >> 5;
    int incl = c;
    #pragma unroll
    for (int o = 1; o < 32; o <<= 1) {
        int t = __shfl_up_sync(0xFFFFFFFFu, incl, o);
        if (lane >= o) incl += t;
    }
    if (lane == 31) wbase[w] = incl;
    __syncthreads();
    if (tid == 0) {
        int s = 0;
        #pragma unroll
        for (int k = 0; k < 8; k++) { int t = wbase[k]; wbase[k] = s; s += t; }
        cnt[row] = s;
    }
    __syncthreads();
    int pos = wbase[w] + incl - c;

    // --- pass 4: write compacted (idx, p) ---
    for (int i = tid; i < N; i += 256) {
        float b = buf[i];
        if (b < 0.0f) {
            float p = (-b) * inv;
            if (p >= P_THRESH) {
                spi[(size_t)row * N + pos] = i;
                spv[(size_t)row * N + pos] = p;
                pos++;
            }
        }
    }
}

// ------------------------- sparse attn -------------------------
__global__ void __launch_bounds__(256)
attn_sparse(const int* __restrict__ spi, const float* __restrict__ spv,
            const int* __restrict__ cnt, const float* __restrict__ corr,
            float* __restrict__ attn)
{
    const int row = blockIdx.x;
    const int tid = threadIdx.x;
    const int n = cnt[row];
    const float4* corr4 = reinterpret_cast<const float4*>(corr);
    float4 acc = make_float4(0.f, 0.f, 0.f, 0.f);
    for (int t = 0; t < n; t++) {
        int   idx = spi[(size_t)row * BATCH + t];
        float v   = spv[(size_t)row * BATCH + t];
        float4 x  = corr4[(size_t)idx * (HIDDIM / 4) + tid];
        acc.x = fmaf(v, x.x, acc.x);
        acc.y = fmaf(v, x.y, acc.y);
        acc.z = fmaf(v, x.z, acc.z);
        acc.w = fmaf(v, x.w, acc.w);
    }
    reinterpret_cast<float4*>(attn)[(size_t)row * (HIDDIM / 4) + tid] = acc;
}

// ------------------------- heads epilogue -------------------------
__global__ void heads_epilogue(const float* __restrict__ logits,
                               const float* __restrict__ attn,
                               const float* __restrict__ W_risk,
                               const float* __restrict__ b_risk,
                               float* __restrict__ probs,
                               float* __restrict__ risk,
                               int B, int D)
{
    int warp = (blockIdx.x * blockDim.x + threadIdx.x) >> 5;
    int lane = threadIdx.x & 31;
    if (warp >= B) return;

    const float* ar = attn + (size_t)warp * D;
    float s = 0.0f;
    for (int k = lane; k < D; k += 32) s = fmaf(ar[k], W_risk[k], s);
    #pragma unroll
    for (int o = 16; o; o >>= 1) s += __shfl_xor_sync(0xFFFFFFFFu, s, o);
    if (lane == 0) risk[warp] = 1.0f / (1.0f + expf(-(s + b_risk[0])));

    const float* lr = logits + (size_t)warp * ACTDIM;
    float v0 = lr[lane], v1 = lr[lane + 32];
    float mx = fmaxf(v0, v1);
    #pragma unroll
    for (int o = 16; o; o >>= 1) mx = fmaxf(mx, __shfl_xor_sync(0xFFFFFFFFu, mx, o));
    float e0 = expf(v0 - mx), e1 = expf(v1 - mx);
    float ss = e0 + e1;
    #pragma unroll
    for (int o = 16; o; o >>= 1) ss += __shfl_xor_sync(0xFFFFFFFFu, ss, o);
    float inv = 1.0f / ss;
    probs[(size_t)warp * ACTDIM + lane]      = e0 * inv;
    probs[(size_t)warp * ACTDIM + lane + 32] = e1 * inv;
}

// ------------------------- launch -------------------------
extern "C" void kernel_launch(void* const* d_in, const int* in_sizes, int n_in,
                              void* d_out, int out_size)
{
    const float* state   = (const float*)d_in[0];
    const float* W_enc   = (const float*)d_in[1];
    const float* b_enc   = (const float*)d_in[2];
    const float* cov     = (const float*)d_in[3];
    const float* W_phase = (const float*)d_in[4];
    const float* b_phase = (const float*)d_in[5];
    const float* cptr    = (const float*)d_in[6];
    const float* W_actor = (const float*)d_in[7];
    const float* b_actor = (const float*)d_in[8];
    const float* W_risk  = (const float*)d_in[9];
    const float* b_risk  = (const float*)d_in[10];

    float* out    = (float*)d_out;
    float* logits = out;
    float* probs  = out + (size_t)BATCH * ACTDIM;
    float* risk   = out + (size_t)2 * BATCH * ACTDIM;

    float *enc, *corr, *attn, *nrm, *rterm, *S, *spv;
    __nv_bfloat16 *corrb, *sth, *stl, *weh, *wel, *cvh, *cvl, *wph, *wpl,
                  *ench, *encl, *t1h, *t1l;
    int *spi, *cnt;
    cudaGetSymbolAddress((void**)&enc,   g_enc);
    cudaGetSymbolAddress((void**)&corr,  g_corr);
    cudaGetSymbolAddress((void**)&corrb, g_corrb);
    cudaGetSymbolAddress((void**)&attn,  g_attn);
    cudaGetSymbolAddress((void**)&nrm,   g_norm);
    cudaGetSymbolAddress((void**)&rterm, g_rterm);
    cudaGetSymbolAddress((void**)&S,     g_S);
    cudaGetSymbolAddress((void**)&spi,   g_spi);
    cudaGetSymbolAddress((void**)&spv,   g_spv);
    cudaGetSymbolAddress((void**)&cnt,   g_cnt);
    cudaGetSymbolAddress((void**)&sth,   g_state_h);
    cudaGetSymbolAddress((void**)&stl,   g_state_l);
    cudaGetSymbolAddress((void**)&weh,   g_Wenc_h);
    cudaGetSymbolAddress((void**)&wel,   g_Wenc_l);
    cudaGetSymbolAddress((void**)&cvh,   g_cov_h);
    cudaGetSymbolAddress((void**)&cvl,   g_cov_l);
    cudaGetSymbolAddress((void**)&wph,   g_Wph_h);
    cudaGetSymbolAddress((void**)&wpl,   g_Wph_l);
    cudaGetSymbolAddress((void**)&ench,  g_enc_h);
    cudaGetSymbolAddress((void**)&encl,  g_enc_l);
    cudaGetSymbolAddress((void**)&t1h,   g_t1_h);
    cudaGetSymbolAddress((void**)&t1l,   g_t1_l);

    // 0) split inputs to (hi, lo) bf16
    split_bf16<<<(BATCH * INDIM)   / 1024, 256>>>(state,   sth, stl);
    split_bf16<<<(INDIM * HIDDIM)  / 1024, 256>>>(W_enc,   weh, wel);
    split_bf16<<<(HIDDIM * HIDDIM) / 1024, 256>>>(cov,     cvh, cvl);
    split_bf16<<<(HIDDIM * HIDDIM) / 1024, 256>>>(W_phase, wph, wpl);

    // 1) enc = relu(state @ W_enc + b_enc)  -> enc fp32 + (hi, lo)
    gemm_split<1><<<dim3(HIDDIM / 128, BATCH / 128), 256>>>(
        sth, stl, weh, wel, enc, ench, encl, BATCH, HIDDIM, INDIM, b_enc, nullptr);

    // 2) t1 = enc @ cov  -> (hi, lo) only
    gemm_split<0><<<dim3(HIDDIM / 128, BATCH / 128), 256>>>(
        ench, encl, cvh, cvl, nullptr, t1h, t1l, BATCH, HIDDIM, HIDDIM, nullptr, nullptr);

    // 3) corr = tanh(t1 @ W_phase + b_phase) + enc  -> corr fp32 + corrb bf16
    gemm_split<2><<<dim3(HIDDIM / 128, BATCH / 128), 256>>>(
        t1h, t1l, wph, wpl, corr, corrb, nullptr, BATCH, HIDDIM, HIDDIM, b_phase, enc);

    // 4) per-row squared norms + 1/term
    row_norms<<<BATCH / 8, 256>>>(corr, nrm, rterm, cptr, BATCH, HIDDIM);

    // 5) S = arg(corr, corr): bf16 HMMA Gram, upper-tri + mirror, MUFU-free epilogue
    gram_arg_wmma<<<NBLK * (NBLK + 1) / 2, 256>>>(
        corrb, S, BATCH, HIDDIM, nrm, rterm, cptr);

    // 6) softmax rows over arg + sparsity compaction (transcendentals on candidates only)
    softmax_compact<<<BATCH, 256>>>(S, spi, spv, cnt, BATCH, cptr);

    // 7) attn = P @ corr (sparse)
    attn_sparse<<<BATCH, 256>>>(spi, spv, cnt, corr, attn);

    // 8) logits = attn @ W_actor + b_actor
    gemm_nn<128, 64, 16, 8, 4><<<dim3(ACTDIM / 64, BATCH / 128), 256>>>(
        attn, W_actor, logits, BATCH, ACTDIM, HIDDIM, b_actor);

    // 9) probs + risk
    heads_epilogue<<<BATCH / 8, 256>>>(logits, attn, W_risk, b_risk, probs, risk, BATCH, HIDDIM);
}

// round 17
// speedup vs baseline: 7.2647x; 1.1370x over previous
#include <cuda_runtime.h>
#include <cuda_bf16.h>
#include <mma.h>
#include <math.h>

using namespace nvcuda;

#define EPSF 1e-6f

#define BATCH 8192
#define INDIM 512
#define HIDDIM 1024
#define ACTDIM 64

// Candidate filter margin in dist units: entries with dist - dist_min > 30
// have softmax weight <= e^-30 ~ 9e-14 each; 8192 of them contribute <= 7.7e-10
// of the softmax sum (which is >= 1 because the diagonal candidate has weight
// exactly 1). Certified for ANY input.
#define CAND_MARGIN 30.0f

#define NBLK (BATCH / 128)

// ------------------------- scratch (no cudaMalloc allowed) -------------------------
__device__ float          g_enc  [(size_t)BATCH * HIDDIM];
__device__ float          g_corr [(size_t)BATCH * HIDDIM];
__device__ __nv_bfloat16  g_corrb[(size_t)BATCH * HIDDIM];
__device__ float          g_attn [(size_t)BATCH * HIDDIM];
__device__ float          g_norm [BATCH];
__device__ float          g_rterm[BATCH];
// candidate lists: per (row, tile-col) fixed capacity of 128 slots
__device__ int            g_spi  [(size_t)BATCH * BATCH];
__device__ float          g_spv  [(size_t)BATCH * BATCH];
__device__ int            g_cnt  [(size_t)BATCH * NBLK];

// split-bf16 operands (hi/lo pairs)
__device__ __nv_bfloat16  g_state_h[(size_t)BATCH * INDIM];
__device__ __nv_bfloat16  g_state_l[(size_t)BATCH * INDIM];
__device__ __nv_bfloat16  g_Wenc_h [(size_t)INDIM * HIDDIM];
__device__ __nv_bfloat16  g_Wenc_l [(size_t)INDIM * HIDDIM];
__device__ __nv_bfloat16  g_cov_h  [(size_t)HIDDIM * HIDDIM];
__device__ __nv_bfloat16  g_cov_l  [(size_t)HIDDIM * HIDDIM];
__device__ __nv_bfloat16  g_Wph_h  [(size_t)HIDDIM * HIDDIM];
__device__ __nv_bfloat16  g_Wph_l  [(size_t)HIDDIM * HIDDIM];
__device__ __nv_bfloat16  g_enc_h  [(size_t)BATCH * HIDDIM];
__device__ __nv_bfloat16  g_enc_l  [(size_t)BATCH * HIDDIM];
__device__ __nv_bfloat16  g_t1_h   [(size_t)BATCH * HIDDIM];
__device__ __nv_bfloat16  g_t1_l   [(size_t)BATCH * HIDDIM];

// ------------------------- fp32 -> (hi, lo) bf16 split -------------------------
__global__ void split_bf16(const float* __restrict__ x,
                           __nv_bfloat16* __restrict__ h,
                           __nv_bfloat16* __restrict__ l)
{
    size_t i = ((size_t)blockIdx.x * blockDim.x + threadIdx.x) * 4;
    float4 v = *reinterpret_cast<const float4*>(&x[i]);
    __nv_bfloat16 hv[4], lv[4];
    float vv[4] = {v.x, v.y, v.z, v.w};
    #pragma unroll
    for (int t = 0; t < 4; t++) {
        hv[t] = __float2bfloat16_rn(vv[t]);
        lv[t] = __float2bfloat16_rn(vv[t] - __bfloat162float(hv[t]));
    }
    *reinterpret_cast<uint2*>(&h[i]) = *reinterpret_cast<uint2*>(hv);
    *reinterpret_cast<uint2*>(&l[i]) = *reinterpret_cast<uint2*>(lv);
}

// ------------------------- split-bf16 wmma GEMM with fused epilogues -------------------------
// (unchanged — proven correct)
template<int SEPI>
__global__ void __launch_bounds__(256)
gemm_split(const __nv_bfloat16* __restrict__ Ah_, const __nv_bfloat16* __restrict__ Al_,
           const __nv_bfloat16* __restrict__ Bh_, const __nv_bfloat16* __restrict__ Bl_,
           float* __restrict__ Cf,
           __nv_bfloat16* __restrict__ Ch, __nv_bfloat16* __restrict__ Cl,
           int M, int N, int K,
           const float* __restrict__ bias, const float* __restrict__ extra)
{
    __shared__ __nv_bfloat16 Ash[128][40];
    __shared__ __nv_bfloat16 Asl[128][40];
    __shared__ __nv_bfloat16 Bsh[32][136];
    __shared__ __nv_bfloat16 Bsl[32][136];
    __shared__ float stage[8][256];

    const int tid  = threadIdx.x;
    const int wid  = tid >> 5;
    const int lane = tid & 31;
    const int warp_m = wid & 1;
    const int warp_n = wid >> 1;
    const int m0 = blockIdx.y * 128;
    const int n0 = blockIdx.x * 128;

    wmma::fragment<wmma::accumulator, 16, 16, 16, float> cf[4][2];
    #pragma unroll
    for (int i = 0; i < 4; i++)
        #pragma unroll
        for (int j = 0; j < 2; j++)
            wmma::fill_fragment(cf[i][j], 0.0f);

    for (int k0 = 0; k0 < K; k0 += 32) {
        #pragma unroll
        for (int it = 0; it < 2; it++) {
            int idx = tid + it * 256;
            int row = idx >> 2, g = idx & 3;
            *reinterpret_cast<uint4*>(&Ash[row][g * 8]) =
                *reinterpret_cast<const uint4*>(&Ah_[(size_t)(m0 + row) * K + k0 + g * 8]);
            *reinterpret_cast<uint4*>(&Asl[row][g * 8]) =
                *reinterpret_cast<const uint4*>(&Al_[(size_t)(m0 + row) * K + k0 + g * 8]);
        }
        #pragma unroll
        for (int it = 0; it < 2; it++) {
            int idx = tid + it * 256;
            int row = idx >> 4, g = idx & 15;
            *reinterpret_cast<uint4*>(&Bsh[row][g * 8]) =
                *reinterpret_cast<const uint4*>(&Bh_[(size_t)(k0 + row) * N + n0 + g * 8]);
            *reinterpret_cast<uint4*>(&Bsl[row][g * 8]) =
                *reinterpret_cast<const uint4*>(&Bl_[(size_t)(k0 + row) * N + n0 + g * 8]);
        }
        __syncthreads();

        #pragma unroll
        for (int ks = 0; ks < 32; ks += 16) {
            wmma::fragment<wmma::matrix_a, 16, 16, 16, __nv_bfloat16, wmma::row_major> ah[4], al[4];
            wmma::fragment<wmma::matrix_b, 16, 16, 16, __nv_bfloat16, wmma::row_major> bh[2], bl[2];
            #pragma unroll
            for (int i = 0; i < 4; i++) {
                wmma::load_matrix_sync(ah[i], &Ash[warp_m * 64 + i * 16][ks], 40);
                wmma::load_matrix_sync(al[i], &Asl[warp_m * 64 + i * 16][ks], 40);
            }
            #pragma unroll
            for (int j = 0; j < 2; j++) {
                wmma::load_matrix_sync(bh[j], &Bsh[ks][warp_n * 32 + j * 16], 136);
                wmma::load_matrix_sync(bl[j], &Bsl[ks][warp_n * 32 + j * 16], 136);
            }
            #pragma unroll
            for (int i = 0; i < 4; i++)
                #pragma unroll
                for (int j = 0; j < 2; j++) {
                    wmma::mma_sync(cf[i][j], ah[i], bh[j], cf[i][j]);
                    wmma::mma_sync(cf[i][j], al[i], bh[j], cf[i][j]);
                    wmma::mma_sync(cf[i][j], ah[i], bl[j], cf[i][j]);
                }
        }
        __syncthreads();
    }

    const int r  = lane >> 1;
    const int c0 = (lane & 1) * 8;
    #pragma unroll
    for (int i = 0; i < 4; i++) {
        #pragma unroll
        for (int j = 0; j < 2; j++) {
            wmma::store_matrix_sync(stage[wid], cf[i][j], 16, wmma::mem_row_major);
            __syncwarp();

            const int m = m0 + warp_m * 64 + i * 16 + r;
            const int n = n0 + warp_n * 32 + j * 16 + c0;
            float v[8];
            *reinterpret_cast<float4*>(&v[0]) =
                *reinterpret_cast<const float4*>(&stage[wid][r * 16 + c0]);
            *reinterpret_cast<float4*>(&v[4]) =
                *reinterpret_cast<const float4*>(&stage[wid][r * 16 + c0 + 4]);

            if constexpr (SEPI == 1) {
                #pragma unroll
                for (int t = 0; t < 8; t++) v[t] = fmaxf(v[t] + bias[n + t], 0.0f);
            }
            if constexpr (SEPI == 2) {
                float ex[8];
                *reinterpret_cast<float4*>(&ex[0]) =
                    *reinterpret_cast<const float4*>(&extra[(size_t)m * N + n]);
                *reinterpret_cast<float4*>(&ex[4]) =
                    *reinterpret_cast<const float4*>(&extra[(size_t)m * N + n + 4]);
                #pragma unroll
                for (int t = 0; t < 8; t++) v[t] = tanhf(v[t] + bias[n + t]) + ex[t];
            }

            if constexpr (SEPI == 1 || SEPI == 2) {
                *reinterpret_cast<float4*>(&Cf[(size_t)m * N + n])     = *reinterpret_cast<float4*>(&v[0]);
                *reinterpret_cast<float4*>(&Cf[(size_t)m * N + n + 4]) = *reinterpret_cast<float4*>(&v[4]);
            }

            if constexpr (SEPI == 2) {
                __nv_bfloat16 hb[8];
                #pragma unroll
                for (int t = 0; t < 8; t++) hb[t] = __float2bfloat16_rn(v[t]);
                *reinterpret_cast<uint4*>(&Ch[(size_t)m * N + n]) = *reinterpret_cast<uint4*>(hb);
            } else {
                __nv_bfloat16 hb[8], lb[8];
                #pragma unroll
                for (int t = 0; t < 8; t++) {
                    hb[t] = __float2bfloat16_rn(v[t]);
                    lb[t] = __float2bfloat16_rn(v[t] - __bfloat162float(hb[t]));
                }
                *reinterpret_cast<uint4*>(&Ch[(size_t)m * N + n]) = *reinterpret_cast<uint4*>(hb);
                *reinterpret_cast<uint4*>(&Cl[(size_t)m * N + n]) = *reinterpret_cast<uint4*>(lb);
            }
            __syncwarp();
        }
    }
}

// ------------------------- small NN GEMM (scalar FFMA) for the actor head -------------------------
template<int BM, int BN, int BK, int TM, int TN>
__global__ void __launch_bounds__(256)
gemm_nn(const float* __restrict__ A, const float* __restrict__ B,
        float* __restrict__ C, int M, int N, int K,
        const float* __restrict__ bias)
{
    __shared__ float As[BK][BM + 4];
    __shared__ float Bs[BK][BN + 4];

    const int tid = threadIdx.x;
    const int m0 = blockIdx.y * BM;
    const int n0 = blockIdx.x * BN;
    constexpr int TX = BN / TN;
    const int tx = tid % TX;
    const int ty = tid / TX;

    float acc[TM][TN] = {};

    constexpr int LA = BM * BK / (4 * 256);
    constexpr int LB = BK * BN / (4 * 256);

    for (int k0 = 0; k0 < K; k0 += BK) {
        #pragma unroll
        for (int i = 0; i < LA; i++) {
            int f4  = tid + i * 256;
            int row = f4 / (BK / 4);
            int c4  = f4 % (BK / 4);
            float4 v = *reinterpret_cast<const float4*>(&A[(size_t)(m0 + row) * K + k0 + c4 * 4]);
            As[c4 * 4 + 0][row] = v.x;
            As[c4 * 4 + 1][row] = v.y;
            As[c4 * 4 + 2][row] = v.z;
            As[c4 * 4 + 3][row] = v.w;
        }
        #pragma unroll
        for (int i = 0; i < LB; i++) {
            int f4  = tid + i * 256;
            int row = f4 / (BN / 4);
            int c4  = f4 % (BN / 4);
            float4 v = *reinterpret_cast<const float4*>(&B[(size_t)(k0 + row) * N + n0 + c4 * 4]);
            *reinterpret_cast<float4*>(&Bs[row][c4 * 4]) = v;
        }
        __syncthreads();

        #pragma unroll
        for (int k = 0; k < BK; k++) {
            float a[TM], b[TN];
            #pragma unroll
            for (int i = 0; i < TM; i++) a[i] = As[k][ty * TM + i];
            #pragma unroll
            for (int j = 0; j < TN; j++) b[j] = Bs[k][tx * TN + j];
            #pragma unroll
            for (int i = 0; i < TM; i++)
                #pragma unroll
                for (int j = 0; j < TN; j++)
                    acc[i][j] = fmaf(a[i], b[j], acc[i][j]);
        }
        __syncthreads();
    }

    #pragma unroll
    for (int i = 0; i < TM; i++) {
        int m = m0 + ty * TM + i;
        #pragma unroll
        for (int j = 0; j < TN; j++) {
            int n = n0 + tx * TN + j;
            C[(size_t)m * N + n] = acc[i][j] + bias[n];
        }
    }
}

// ------------------------- Gram -> candidate emission (no S matrix) -------------------------
// Upper-triangular 128x128 blocks. Mainloop: bf16 HMMA. Epilogue: stage the arg
// tile in SMEM (stride 132 floats), then scan rows (normal tile) and columns
// (mirror tile) emitting softmax candidates directly into fixed per-(row,tile)
// slots of capacity 128 (cannot overflow; worst case degrades to dense gather).
//
// Key identities (certified for any input):
//  - the epilogue clamp forces arg >= (1+EPSF)+EPSF for every element, and the
//    exact-zero diagonal achieves it -> the row max of s = -acosh(arg)/sqrt(c)
//    is the CONSTANT smax = -acosh((1+EPSF)+EPSF)/sqrt(c). Softmax is
//    shift-invariant, so shifting by smax is exact.
//  - entries with arg > th = cosh(acosh0 + CAND_MARGIN*sqrt(c)) have weight
//    <= e^-CAND_MARGIN; all 8192 together contribute <= 7.7e-10 of the sum
//    (sum >= 1 via the diagonal candidate, weight exactly 1).
#define GBK 64
#define GR_AS_OFF   0
#define GR_BS_OFF   18432
#define GR_STG_OFF  0
#define GR_AUX_OFF  67584            // 128*132*4
#define GR_SMEM_TOTAL (67584 + 2048) // stage + 4x128 floats aux
__global__ void __launch_bounds__(256)
gram_cand_wmma(const __nv_bfloat16* __restrict__ Abf,
               int* __restrict__ spi, float* __restrict__ spv,
               int* __restrict__ cnt,
               int K,
               const float* __restrict__ norm, const float* __restrict__ rterm,
               const float* __restrict__ cptr)
{
    extern __shared__ char dsm[];
    __nv_bfloat16* As = reinterpret_cast<__nv_bfloat16*>(dsm + GR_AS_OFF); // [128][72]
    __nv_bfloat16* Bs = reinterpret_cast<__nv_bfloat16*>(dsm + GR_BS_OFF); // [128][72]
    float* stg   = reinterpret_cast<float*>(dsm + GR_STG_OFF);             // [128][132]
    float* nrm_m = reinterpret_cast<float*>(dsm + GR_AUX_OFF);
    float* rt_m  = reinterpret_cast<float*>(dsm + GR_AUX_OFF + 512);
    float* nrm_n = reinterpret_cast<float*>(dsm + GR_AUX_OFF + 1024);
    float* rt_n  = reinterpret_cast<float*>(dsm + GR_AUX_OFF + 1536);

    const int tid = threadIdx.x;
    const int wid = tid >> 5;
    const int warp_m = wid & 1;
    const int warp_n = wid >> 1;

    // --- triangular block decode: blockIdx.x -> (bm, bn), bm <= bn ---
    const int t = blockIdx.x;
    int bm = (int)(((2.0f * NBLK + 1.0f) -
                    sqrtf((float)((2 * NBLK + 1) * (2 * NBLK + 1) - 8 * t))) * 0.5f);
    if (bm < 0) bm = 0;
    if (bm >= NBLK) bm = NBLK - 1;
    #pragma unroll 1
    while (bm + 1 < NBLK && ((bm + 1) * NBLK - (bm * (bm + 1)) / 2) <= t) bm++;
    #pragma unroll 1
    while (bm > 0 && (bm * NBLK - ((bm - 1) * bm) / 2) > t) bm--;
    const int bn = bm + (t - (bm * NBLK - ((bm - 1) * bm) / 2));

    const int m0 = bm * 128;
    const int n0 = bn * 128;

    wmma::fragment<wmma::accumulator, 16, 16, 16, float> cf[4][2];
    #pragma unroll
    for (int i = 0; i < 4; i++)
        #pragma unroll
        for (int j = 0; j < 2; j++)
            wmma::fill_fragment(cf[i][j], 0.0f);

    for (int k0 = 0; k0 < K; k0 += GBK) {
        #pragma unroll
        for (int i = 0; i < 4; i++) {
            int idx = tid + i * 256;
            int row = idx >> 3;
            int g   = idx & 7;
            *reinterpret_cast<uint4*>(&As[row * 72 + g * 8]) =
                *reinterpret_cast<const uint4*>(&Abf[(size_t)(m0 + row) * K + k0 + g * 8]);
        }
        #pragma unroll
        for (int i = 0; i < 4; i++) {
            int idx = tid + i * 256;
            int row = idx >> 3;
            int g   = idx & 7;
            *reinterpret_cast<uint4*>(&Bs[row * 72 + g * 8]) =
                *reinterpret_cast<const uint4*>(&Abf[(size_t)(n0 + row) * K + k0 + g * 8]);
        }
        __syncthreads();

        #pragma unroll
        for (int ks = 0; ks < GBK; ks += 16) {
            wmma::fragment<wmma::matrix_a, 16, 16, 16, __nv_bfloat16, wmma::row_major> af[4];
            wmma::fragment<wmma::matrix_b, 16, 16, 16, __nv_bfloat16, wmma::col_major> bf[2];
            #pragma unroll
            for (int i = 0; i < 4; i++)
                wmma::load_matrix_sync(af[i], &As[(warp_m * 64 + i * 16) * 72 + ks], 72);
            #pragma unroll
            for (int j = 0; j < 2; j++)
                wmma::load_matrix_sync(bf[j], &Bs[(warp_n * 32 + j * 16) * 72 + ks], 72);
            #pragma unroll
            for (int i = 0; i < 4; i++)
                #pragma unroll
                for (int j = 0; j < 2; j++)
                    wmma::mma_sync(cf[i][j], af[i], bf[j], cf[i][j]);
        }
        __syncthreads();
    }

    // --- stage raw Gram into SMEM (stride 132) ---
    #pragma unroll
    for (int i = 0; i < 4; i++) {
        #pragma unroll
        for (int j = 0; j < 2; j++) {
            float* dst = &stg[(warp_m * 64 + i * 16) * 132 + warp_n * 32 + j * 16];
            wmma::store_matrix_sync(dst, cf[i][j], 132, wmma::mem_row_major);
        }
    }
    // aux loads (region disjoint from stage)
    if (tid < 128) {
        nrm_m[tid] = norm[m0 + tid];
        rt_m[tid]  = rterm[m0 + tid];
    } else {
        nrm_n[tid - 128] = norm[n0 + tid - 128];
        rt_n[tid - 128]  = rterm[n0 + tid - 128];
    }
    __syncthreads();

    const float cc     = fmaxf(cptr[0], EPSF);
    const float isc    = rsqrtf(cc);
    const float two_cc = 2.0f * cc;
    const float acosh0 = acoshf((1.0f + EPSF) + EPSF);
    const float th     = coshf(acosh0 + CAND_MARGIN * sqrtf(cc));
    const bool  diag   = (bm == bn);

    // --- convert raw g -> arg in place ---
    for (int idx = tid; idx < 128 * 128; idx += 256) {
        int i = idx >> 7, j = idx & 127;
        float g  = stg[i * 132 + j];
        float d2 = (diag && i == j) ? 0.0f
                 : fmaxf(nrm_m[i] + nrm_n[j] - 2.0f * g, 0.0f);
        float arg = fmaf(two_cc * d2, rt_m[i] * rt_n[j], 1.0f);
        arg = fmaxf(arg, 1.0f + EPSF) + EPSF;
        stg[i * 132 + j] = arg;
    }
    __syncthreads();

    // --- candidate emission ---
    if (tid < 128) {
        // normal tile: row m = m0+tid, scan 128 columns (ascending j = deterministic)
        const int m = m0 + tid;
        const size_t base = ((size_t)m * NBLK + bn) * 128;
        int c = 0;
        #pragma unroll 4
        for (int j = 0; j < 128; j++) {
            float a = stg[tid * 132 + j];
            if (a <= th) {
                spi[base + c] = n0 + j;
                spv[base + c] = expf((acosh0 - acoshf(a)) * isc);
                c++;
            }
        }
        cnt[(size_t)m * NBLK + bn] = c;
    } else if (!diag) {
        // mirror tile: row n = n0+(tid-128), scan 128 m-indices (ascending i)
        const int jj = tid - 128;
        const int n = n0 + jj;
        const size_t base = ((size_t)n * NBLK + bm) * 128;
        int c = 0;
        #pragma unroll 4
        for (int i = 0; i < 128; i++) {
            float a = stg[i * 132 + jj];
            if (a <= th) {
                spi[base + c] = m0 + i;
                spv[base + c] = expf((acosh0 - acoshf(a)) * isc);
                c++;
            }
        }
        cnt[(size_t)n * NBLK + bm] = c;
    }
}

// ------------------------- row squared norms + 1/term -------------------------
__global__ void row_norms(const float* __restrict__ X, float* __restrict__ norm,
                          float* __restrict__ rterm,
                          const float* __restrict__ cptr, int B, int D)
{
    int warp = (blockIdx.x * blockDim.x + threadIdx.x) >> 5;
    int lane = threadIdx.x & 31;
    if (warp >= B) return;
    const float* x = X + (size_t)warp * D;
    float s = 0.0f;
    for (int k = lane; k < D; k += 32) { float v = x[k]; s = fmaf(v, v, s); }
    #pragma unroll
    for (int o = 16; o; o >>= 1) s += __shfl_xor_sync(0xFFFFFFFFu, s, o);
    if (lane == 0) {
        norm[warp] = s;
        float cc = fmaxf(cptr[0], EPSF);
        float t  = fmaxf(1.0f - cc * s, EPSF);
        rterm[warp] = 1.0f / t;
    }
}

// ------------------------- attn gather: attn[r,:] = (sum_t e_t * corr[idx_t,:]) / sum_t e_t ----
// Deterministic: candidates visited in fixed (tile, slot) order; the weight sum
// is accumulated identically (and redundantly) by every thread.
__global__ void __launch_bounds__(256)
attn_gather(const int* __restrict__ spi, const float* __restrict__ spv,
            const int* __restrict__ cnt, const float* __restrict__ corr,
            float* __restrict__ attn)
{
    const int row = blockIdx.x;
    const int tid = threadIdx.x;
    const float4* corr4 = reinterpret_cast<const float4*>(corr);
    float4 acc = make_float4(0.f, 0.f, 0.f, 0.f);
    float sum = 0.0f;

    #pragma unroll 1
    for (int bn = 0; bn < NBLK; bn++) {
        const int c = cnt[(size_t)row * NBLK + bn];
        const size_t base = ((size_t)row * NBLK + bn) * 128;
        for (int k = 0; k < c; k++) {
            int   idx = spi[base + k];
            float e   = spv[base + k];
            sum += e;
            float4 x = corr4[(size_t)idx * (HIDDIM / 4) + tid];
            acc.x = fmaf(e, x.x, acc.x);
            acc.y = fmaf(e, x.y, acc.y);
            acc.z = fmaf(e, x.z, acc.z);
            acc.w = fmaf(e, x.w, acc.w);
        }
    }
    const float inv = 1.0f / sum;   // sum >= 1 (diagonal candidate has weight 1)
    acc.x *= inv; acc.y *= inv; acc.z *= inv; acc.w *= inv;
    reinterpret_cast<float4*>(attn)[(size_t)row * (HIDDIM / 4) + tid] = acc;
}

// ------------------------- heads epilogue -------------------------
__global__ void heads_epilogue(const float* __restrict__ logits,
                               const float* __restrict__ attn,
                               const float* __restrict__ W_risk,
                               const float* __restrict__ b_risk,
                               float* __restrict__ probs,
                               float* __restrict__ risk,
                               int B, int D)
{
    int warp = (blockIdx.x * blockDim.x + threadIdx.x) >> 5;
    int lane = threadIdx.x & 31;
    if (warp >= B) return;

    const float* ar = attn + (size_t)warp * D;
    float s = 0.0f;
    for (int k = lane; k < D; k += 32) s = fmaf(ar[k], W_risk[k], s);
    #pragma unroll
    for (int o = 16; o; o >>= 1) s += __shfl_xor_sync(0xFFFFFFFFu, s, o);
    if (lane == 0) risk[warp] = 1.0f / (1.0f + expf(-(s + b_risk[0])));

    const float* lr = logits + (size_t)warp * ACTDIM;
    float v0 = lr[lane], v1 = lr[lane + 32];
    float mx = fmaxf(v0, v1);
    #pragma unroll
    for (int o = 16; o; o >>= 1) mx = fmaxf(mx, __shfl_xor_sync(0xFFFFFFFFu, mx, o));
    float e0 = expf(v0 - mx), e1 = expf(v1 - mx);
    float ss = e0 + e1;
    #pragma unroll
    for (int o = 16; o; o >>= 1) ss += __shfl_xor_sync(0xFFFFFFFFu, ss, o);
    float inv = 1.0f / ss;
    probs[(size_t)warp * ACTDIM + lane]      = e0 * inv;
    probs[(size_t)warp * ACTDIM + lane + 32] = e1 * inv;
}

// ------------------------- launch -------------------------
extern "C" void kernel_launch(void* const* d_in, const int* in_sizes, int n_in,
                              void* d_out, int out_size)
{
    const float* state   = (const float*)d_in[0];
    const float* W_enc   = (const float*)d_in[1];
    const float* b_enc   = (const float*)d_in[2];
    const float* cov     = (const float*)d_in[3];
    const float* W_phase = (const float*)d_in[4];
    const float* b_phase = (const float*)d_in[5];
    const float* cptr    = (const float*)d_in[6];
    const float* W_actor = (const float*)d_in[7];
    const float* b_actor = (const float*)d_in[8];
    const float* W_risk  = (const float*)d_in[9];
    const float* b_risk  = (const float*)d_in[10];

    float* out    = (float*)d_out;
    float* logits = out;
    float* probs  = out + (size_t)BATCH * ACTDIM;
    float* risk   = out + (size_t)2 * BATCH * ACTDIM;

    float *enc, *corr, *attn, *nrm, *rterm, *spv;
    __nv_bfloat16 *corrb, *sth, *stl, *weh, *wel, *cvh, *cvl, *wph, *wpl,
                  *ench, *encl, *t1h, *t1l;
    int *spi, *cnt;
    cudaGetSymbolAddress((void**)&enc,   g_enc);
    cudaGetSymbolAddress((void**)&corr,  g_corr);
    cudaGetSymbolAddress((void**)&corrb, g_corrb);
    cudaGetSymbolAddress((void**)&attn,  g_attn);
    cudaGetSymbolAddress((void**)&nrm,   g_norm);
    cudaGetSymbolAddress((void**)&rterm, g_rterm);
    cudaGetSymbolAddress((void**)&spi,   g_spi);
    cudaGetSymbolAddress((void**)&spv,   g_spv);
    cudaGetSymbolAddress((void**)&cnt,   g_cnt);
    cudaGetSymbolAddress((void**)&sth,   g_state_h);
    cudaGetSymbolAddress((void**)&stl,   g_state_l);
    cudaGetSymbolAddress((void**)&weh,   g_Wenc_h);
    cudaGetSymbolAddress((void**)&wel,   g_Wenc_l);
    cudaGetSymbolAddress((void**)&cvh,   g_cov_h);
    cudaGetSymbolAddress((void**)&cvl,   g_cov_l);
    cudaGetSymbolAddress((void**)&wph,   g_Wph_h);
    cudaGetSymbolAddress((void**)&wpl,   g_Wph_l);
    cudaGetSymbolAddress((void**)&ench,  g_enc_h);
    cudaGetSymbolAddress((void**)&encl,  g_enc_l);
    cudaGetSymbolAddress((void**)&t1h,   g_t1_h);
    cudaGetSymbolAddress((void**)&t1l,   g_t1_l);

    // 0) split inputs to (hi, lo) bf16
    split_bf16<<<(BATCH * INDIM)   / 1024, 256>>>(state,   sth, stl);
    split_bf16<<<(INDIM * HIDDIM)  / 1024, 256>>>(W_enc,   weh, wel);
    split_bf16<<<(HIDDIM * HIDDIM) / 1024, 256>>>(cov,     cvh, cvl);
    split_bf16<<<(HIDDIM * HIDDIM) / 1024, 256>>>(W_phase, wph, wpl);

    // 1) enc = relu(state @ W_enc + b_enc)  -> enc fp32 + (hi, lo)
    gemm_split<1><<<dim3(HIDDIM / 128, BATCH / 128), 256>>>(
        sth, stl, weh, wel, enc, ench, encl, BATCH, HIDDIM, INDIM, b_enc, nullptr);

    // 2) t1 = enc @ cov  -> (hi, lo) only
    gemm_split<0><<<dim3(HIDDIM / 128, BATCH / 128), 256>>>(
        ench, encl, cvh, cvl, nullptr, t1h, t1l, BATCH, HIDDIM, HIDDIM, nullptr, nullptr);

    // 3) corr = tanh(t1 @ W_phase + b_phase) + enc  -> corr fp32 + corrb bf16
    gemm_split<2><<<dim3(HIDDIM / 128, BATCH / 128), 256>>>(
        t1h, t1l, wph, wpl, corr, corrb, nullptr, BATCH, HIDDIM, HIDDIM, b_phase, enc);

    // 4) per-row squared norms + 1/term
    row_norms<<<BATCH / 8, 256>>>(corr, nrm, rterm, cptr, BATCH, HIDDIM);

    // 5) Gram + hyperbolic distance + softmax candidate emission, no S matrix
    cudaFuncSetAttribute(gram_cand_wmma,
                         cudaFuncAttributeMaxDynamicSharedMemorySize, GR_SMEM_TOTAL);
    gram_cand_wmma<<<NBLK * (NBLK + 1) / 2, 256, GR_SMEM_TOTAL>>>(
        corrb, spi, spv, cnt, HIDDIM, nrm, rterm, cptr);

    // 6) attn = normalized candidate gather
    attn_gather<<<BATCH, 256>>>(spi, spv, cnt, corr, attn);

    // 7) logits = attn @ W_actor + b_actor
    gemm_nn<128, 64, 16, 8, 4><<<dim3(ACTDIM / 64, BATCH / 128), 256>>>(
        attn, W_actor, logits, BATCH, ACTDIM, HIDDIM, b_actor);

    // 8) probs + risk
    heads_epilogue<<<BATCH / 8, 256>>>(logits, attn, W_risk, b_risk, probs, risk, BATCH, HIDDIM);
}